// round 2
// baseline (speedup 1.0000x reference)
#include <cuda_runtime.h>
#include <cuda_bf16.h>

#define BN 16384
#define HN 128
#define PREDN 12

// ---------------- device scratch ----------------
__device__ float g_Wp[128 * 512];   // permuted W_hh^T: Wp[k][n], n = unit*4 + gate
__device__ float g_Mc[2 * 512];     // folded x-path matrix (W_emb @ W_ih^T), permuted cols
__device__ float g_bv[512];         // folded bias (b_emb@W_ih^T + b_ih + b_hh), permuted
__device__ float g_W1[128 * 64];    // GAT layer1 weights K-major: W1[c][head*16+f]
__device__ float g_h[BN * HN];      // hidden state (GAT output / h0)
__device__ float g_c[BN * HN];      // LSTM cell state
__device__ float g_hpre[BN * HN];   // goal-gated LSTM h (input to GAT)
__device__ float g_x[BN * 64];      // GAT layer-1 output (elu, heads concat)
__device__ float g_gls[PREDN * BN]; // goal softmax log-denominator per (t,row)

__device__ __forceinline__ float fsig(float x) {
    return __fdividef(1.f, 1.f + __expf(-x));
}
__device__ __forceinline__ float ftanh(float x) {
    return __fdividef(2.f, 1.f + __expf(-2.f * x)) - 1.f;
}

// ---------------- setup: permutation + algebraic folding ----------------
__global__ void setup_kernel(const float* __restrict__ W_emb, const float* __restrict__ b_emb,
                             const float* __restrict__ W_ih, const float* __restrict__ W_hh,
                             const float* __restrict__ b_ih, const float* __restrict__ b_hh,
                             const float* __restrict__ w1) {
    int idx = blockIdx.x * 256 + threadIdx.x;   // 65536 threads
    if (idx < 128 * 512) {
        int k = idx >> 9, n = idx & 511;
        int u = n >> 2, g = n & 3;
        g_Wp[idx] = W_hh[(g * 128 + u) * 128 + k];
    }
    if (idx < 128 * 64) {
        int c = idx >> 6, kf = idx & 63;
        int hd = kf >> 4, f = kf & 15;
        g_W1[idx] = w1[(hd * 128 + c) * 16 + f];
    }
    if (idx < 512) {
        int n = idx;
        int u = n >> 2, g = n & 3;
        int row = g * 128 + u;
        float m0 = 0.f, m1 = 0.f, bb = 0.f;
        for (int e = 0; e < 64; e++) {
            float wih = W_ih[row * 64 + e];
            m0 += W_emb[e] * wih;
            m1 += W_emb[64 + e] * wih;
            bb += b_emb[e] * wih;
        }
        g_Mc[n] = m0;
        g_Mc[512 + n] = m1;
        g_bv[n] = bb + b_ih[row] + b_hh[row];
    }
}

__global__ void init_kernel(const float* __restrict__ h0) {
    int i = blockIdx.x * 256 + threadIdx.x;
    if (i < BN * HN) { g_h[i] = h0[i]; g_c[i] = 0.f; }
}

// one warp per (t,row): log-sum-exp of goal logits over 128 units
__global__ void gls_kernel(const float* __restrict__ pred_goal, const float* __restrict__ W_goal,
                           const float* __restrict__ b_goal) {
    int gw = (blockIdx.x * 256 + threadIdx.x) >> 5;
    int lane = threadIdx.x & 31;
    if (gw >= PREDN * BN) return;
    float pg0 = pred_goal[gw * 2 + 0], pg1 = pred_goal[gw * 2 + 1];
    float z[4];
    float m = -1e30f;
#pragma unroll
    for (int q = 0; q < 4; q++) {
        int u = lane + q * 32;
        z[q] = pg0 * W_goal[u] + pg1 * W_goal[128 + u] + b_goal[u];
        m = fmaxf(m, z[q]);
    }
#pragma unroll
    for (int s = 16; s > 0; s >>= 1) m = fmaxf(m, __shfl_xor_sync(0xffffffffu, m, s));
    float sum = 0.f;
#pragma unroll
    for (int q = 0; q < 4; q++) sum += __expf(z[q] - m);
#pragma unroll
    for (int s = 16; s > 0; s >>= 1) sum += __shfl_xor_sync(0xffffffffu, sum, s);
    if (lane == 0) g_gls[gw] = m + __logf(sum);
}

// ---------------- fused LSTM: h@Wp GEMM + cell update + goal gate ----------------
__global__ __launch_bounds__(256) void lstm_kernel(int t,
                                                   const float* __restrict__ action_real,
                                                   const float* __restrict__ pred_goal,
                                                   const float* __restrict__ W_goal,
                                                   const float* __restrict__ b_goal) {
    __shared__ __align__(16) float As[32][132];
    __shared__ float4 Bs[32][32];
    __shared__ float arS[128][2];
    __shared__ float pgS[128][2];
    __shared__ float glsS[128];

    int tid = threadIdx.x;
    int tx = tid & 15, ty = tid >> 4;
    int m0 = blockIdx.y * 128;
    int n0 = blockIdx.x * 128;
    int nb = n0 + tx * 8;

    float mc0[8], mc1[8], bvv[8];
#pragma unroll
    for (int j = 0; j < 8; j++) {
        mc0[j] = g_Mc[nb + j];
        mc1[j] = g_Mc[512 + nb + j];
        bvv[j] = g_bv[nb + j];
    }
    int u0 = (n0 >> 2) + 2 * tx;
    float wg0a = W_goal[u0], wg0b = W_goal[u0 + 1];
    float wg1a = W_goal[128 + u0], wg1b = W_goal[128 + u0 + 1];
    float bga = b_goal[u0], bgb = b_goal[u0 + 1];

    {
        int r = tid >> 1, cmp = tid & 1;
        arS[r][cmp] = action_real[(((8 + t) * BN) + m0 + r) * 2 + cmp];
        pgS[r][cmp] = pred_goal[((t * BN) + m0 + r) * 2 + cmp];
        if (tid < 128) glsS[tid] = g_gls[t * BN + m0 + tid];
    }

    float acc[8][8];
#pragma unroll
    for (int i = 0; i < 8; i++)
#pragma unroll
        for (int j = 0; j < 8; j++) acc[i][j] = 0.f;

    for (int kc = 0; kc < 4; kc++) {
        int k0 = kc * 32;
        __syncthreads();
#pragma unroll
        for (int it = 0; it < 4; it++) {
            int idx = it * 256 + tid;
            int r = idx >> 3, kq = idx & 7;
            float4 v = *reinterpret_cast<const float4*>(&g_h[(m0 + r) * 128 + k0 + kq * 4]);
            As[kq * 4 + 0][r] = v.x;
            As[kq * 4 + 1][r] = v.y;
            As[kq * 4 + 2][r] = v.z;
            As[kq * 4 + 3][r] = v.w;
        }
#pragma unroll
        for (int it = 0; it < 4; it++) {
            int idx = it * 256 + tid;
            int k = idx >> 5, nq = idx & 31;
            Bs[k][nq] = *reinterpret_cast<const float4*>(&g_Wp[(k0 + k) * 512 + n0 + nq * 4]);
        }
        __syncthreads();
#pragma unroll
        for (int k = 0; k < 32; k++) {
            float4 a0 = *reinterpret_cast<const float4*>(&As[k][ty * 8]);
            float4 a1 = *reinterpret_cast<const float4*>(&As[k][ty * 8 + 4]);
            float4 b0 = Bs[k][tx * 2], b1 = Bs[k][tx * 2 + 1];
            float av[8] = {a0.x, a0.y, a0.z, a0.w, a1.x, a1.y, a1.z, a1.w};
            float bw[8] = {b0.x, b0.y, b0.z, b0.w, b1.x, b1.y, b1.z, b1.w};
#pragma unroll
            for (int i = 0; i < 8; i++)
#pragma unroll
                for (int j = 0; j < 8; j++) acc[i][j] += av[i] * bw[j];
        }
    }

    // epilogue: 2 units x 4 interleaved gates per thread, 8 rows
#pragma unroll
    for (int i = 0; i < 8; i++) {
        int rr = ty * 8 + i;
        int r = m0 + rr;
        float ar0 = arS[rr][0], ar1 = arS[rr][1];
        float pg0 = pgS[rr][0], pg1 = pgS[rr][1];
        float gls = glsS[rr];
        float2 cold = *reinterpret_cast<const float2*>(&g_c[r * 128 + u0]);
        float hv[2], cn[2];
#pragma unroll
        for (int p = 0; p < 2; p++) {
            int jb = p * 4;
            float gi = acc[i][jb + 0] + ar0 * mc0[jb + 0] + ar1 * mc1[jb + 0] + bvv[jb + 0];
            float gf = acc[i][jb + 1] + ar0 * mc0[jb + 1] + ar1 * mc1[jb + 1] + bvv[jb + 1];
            float gg = acc[i][jb + 2] + ar0 * mc0[jb + 2] + ar1 * mc1[jb + 2] + bvv[jb + 2];
            float go = acc[i][jb + 3] + ar0 * mc0[jb + 3] + ar1 * mc1[jb + 3] + bvv[jb + 3];
            float co = (p == 0) ? cold.x : cold.y;
            float cnv = fsig(gf) * co + fsig(gi) * ftanh(gg);
            float h1 = fsig(go) * ftanh(cnv);
            float z = (p == 0) ? (pg0 * wg0a + pg1 * wg1a + bga)
                               : (pg0 * wg0b + pg1 * wg1b + bgb);
            h1 *= __expf(z - gls);
            hv[p] = h1;
            cn[p] = cnv;
        }
        *reinterpret_cast<float2*>(&g_c[r * 128 + u0]) = make_float2(cn[0], cn[1]);
        *reinterpret_cast<float2*>(&g_hpre[r * 128 + u0]) = make_float2(hv[0], hv[1]);
    }
}

// ---------------- GAT layer 1: hpre@W1 GEMM + fused per-group attention + elu ----------------
// 256 thr: tx(16) x 4 cols covering N=64; ty(16) x 8 rows = one group each
__global__ __launch_bounds__(256) void gat1_kernel(const float* __restrict__ a_src1,
                                                   const float* __restrict__ a_dst1,
                                                   const float* __restrict__ bias1) {
    __shared__ __align__(16) float As[32][132];
    __shared__ float4 Bs1[32][16];

    int tid = threadIdx.x;
    int tx = tid & 15, ty = tid >> 4;
    int m0 = blockIdx.x * 128;
    int col0 = tx * 4;
    int hd = tx >> 2;
    int fb = (tx & 3) * 4;

    float asv[4], adv[4], b1v[4];
#pragma unroll
    for (int j = 0; j < 4; j++) {
        asv[j] = a_src1[hd * 16 + fb + j];
        adv[j] = a_dst1[hd * 16 + fb + j];
        b1v[j] = bias1[fb + j];
    }

    float acc[8][4];
#pragma unroll
    for (int i = 0; i < 8; i++)
#pragma unroll
        for (int j = 0; j < 4; j++) acc[i][j] = 0.f;

    for (int kc = 0; kc < 4; kc++) {
        int k0 = kc * 32;
        __syncthreads();
#pragma unroll
        for (int it = 0; it < 4; it++) {
            int idx = it * 256 + tid;
            int r = idx >> 3, kq = idx & 7;
            float4 v = *reinterpret_cast<const float4*>(&g_hpre[(m0 + r) * 128 + k0 + kq * 4]);
            As[kq * 4 + 0][r] = v.x;
            As[kq * 4 + 1][r] = v.y;
            As[kq * 4 + 2][r] = v.z;
            As[kq * 4 + 3][r] = v.w;
        }
#pragma unroll
        for (int it = 0; it < 2; it++) {
            int idx = it * 256 + tid;
            int k = idx >> 4, q = idx & 15;
            Bs1[k][q] = *reinterpret_cast<const float4*>(&g_W1[(k0 + k) * 64 + q * 4]);
        }
        __syncthreads();
#pragma unroll
        for (int k = 0; k < 32; k++) {
            float4 a0 = *reinterpret_cast<const float4*>(&As[k][ty * 8]);
            float4 a1 = *reinterpret_cast<const float4*>(&As[k][ty * 8 + 4]);
            float4 b = Bs1[k][tx];
            float av[8] = {a0.x, a0.y, a0.z, a0.w, a1.x, a1.y, a1.z, a1.w};
            float bw[4] = {b.x, b.y, b.z, b.w};
#pragma unroll
            for (int i = 0; i < 8; i++)
#pragma unroll
                for (int j = 0; j < 4; j++) acc[i][j] += av[i] * bw[j];
        }
    }

    // attention within the group (8 agents), per head (4 tx-lanes share a head)
    float src[8], dst[8];
#pragma unroll
    for (int n = 0; n < 8; n++) {
        float ps = 0.f, pd = 0.f;
#pragma unroll
        for (int j = 0; j < 4; j++) { ps += acc[n][j] * asv[j]; pd += acc[n][j] * adv[j]; }
        src[n] = ps; dst[n] = pd;
    }
#pragma unroll
    for (int off = 1; off <= 2; off <<= 1) {
#pragma unroll
        for (int n = 0; n < 8; n++) {
            src[n] += __shfl_xor_sync(0xffffffffu, src[n], off);
            dst[n] += __shfl_xor_sync(0xffffffffu, dst[n], off);
        }
    }
#pragma unroll
    for (int n = 0; n < 8; n++) {
        float e[8], mx = -1e30f;
#pragma unroll
        for (int m = 0; m < 8; m++) {
            float z = src[n] + dst[m];
            z = (z >= 0.f) ? z : 0.2f * z;
            e[m] = z;
            mx = fmaxf(mx, z);
        }
        float s = 0.f;
#pragma unroll
        for (int m = 0; m < 8; m++) { e[m] = __expf(e[m] - mx); s += e[m]; }
        float inv = __fdividef(1.f, s);
        float o[4] = {0.f, 0.f, 0.f, 0.f};
#pragma unroll
        for (int m = 0; m < 8; m++) {
            float w = e[m] * inv;
#pragma unroll
            for (int j = 0; j < 4; j++) o[j] += w * acc[m][j];
        }
        float4 xo;
        float* xp = &xo.x;
#pragma unroll
        for (int j = 0; j < 4; j++) {
            float v = o[j] + b1v[j];
            xp[j] = (v > 0.f) ? v : (__expf(v) - 1.f);
        }
        *reinterpret_cast<float4*>(&g_x[(m0 + ty * 8 + n) * 64 + col0]) = xo;
    }
}

// ---------------- GAT layer 2: x@w2 GEMM + attention + W_pos output ----------------
// 256 thr: tx(16) x 8 cols covering N=128; ty(16) x 8 rows = one group each
__global__ __launch_bounds__(256) void gat2_kernel(int t,
                                                   const float* __restrict__ w2,
                                                   const float* __restrict__ a_src2,
                                                   const float* __restrict__ a_dst2,
                                                   const float* __restrict__ bias2,
                                                   const float* __restrict__ W_pos,
                                                   const float* __restrict__ b_pos,
                                                   float* __restrict__ out) {
    __shared__ __align__(16) float As[32][132];
    __shared__ float4 Bs[32][32];

    int tid = threadIdx.x;
    int tx = tid & 15, ty = tid >> 4;
    int m0 = blockIdx.x * 128;
    int o0 = tx * 8;

    float asv[8], adv[8], b2v[8], wp0[8], wp1[8];
#pragma unroll
    for (int j = 0; j < 8; j++) {
        asv[j] = a_src2[o0 + j];
        adv[j] = a_dst2[o0 + j];
        b2v[j] = bias2[o0 + j];
        wp0[j] = W_pos[(o0 + j) * 2 + 0];
        wp1[j] = W_pos[(o0 + j) * 2 + 1];
    }

    float acc[8][8];
#pragma unroll
    for (int i = 0; i < 8; i++)
#pragma unroll
        for (int j = 0; j < 8; j++) acc[i][j] = 0.f;

    for (int kc = 0; kc < 2; kc++) {
        int k0 = kc * 32;
        __syncthreads();
#pragma unroll
        for (int it = 0; it < 4; it++) {
            int idx = it * 256 + tid;
            int r = idx >> 3, kq = idx & 7;
            float4 v = *reinterpret_cast<const float4*>(&g_x[(m0 + r) * 64 + k0 + kq * 4]);
            As[kq * 4 + 0][r] = v.x;
            As[kq * 4 + 1][r] = v.y;
            As[kq * 4 + 2][r] = v.z;
            As[kq * 4 + 3][r] = v.w;
        }
#pragma unroll
        for (int it = 0; it < 4; it++) {
            int idx = it * 256 + tid;
            int k = idx >> 5, q = idx & 31;
            Bs[k][q] = *reinterpret_cast<const float4*>(&w2[(k0 + k) * 128 + q * 4]);
        }
        __syncthreads();
#pragma unroll
        for (int k = 0; k < 32; k++) {
            float4 a0 = *reinterpret_cast<const float4*>(&As[k][ty * 8]);
            float4 a1 = *reinterpret_cast<const float4*>(&As[k][ty * 8 + 4]);
            float4 b0 = Bs[k][tx * 2], b1 = Bs[k][tx * 2 + 1];
            float av[8] = {a0.x, a0.y, a0.z, a0.w, a1.x, a1.y, a1.z, a1.w};
            float bw[8] = {b0.x, b0.y, b0.z, b0.w, b1.x, b1.y, b1.z, b1.w};
#pragma unroll
            for (int i = 0; i < 8; i++)
#pragma unroll
                for (int j = 0; j < 8; j++) acc[i][j] += av[i] * bw[j];
        }
    }

    // attention over the group (single head, 16 tx lanes share it)
    float src[8], dst[8];
#pragma unroll
    for (int n = 0; n < 8; n++) {
        float ps = 0.f, pd = 0.f;
#pragma unroll
        for (int j = 0; j < 8; j++) { ps += acc[n][j] * asv[j]; pd += acc[n][j] * adv[j]; }
        src[n] = ps; dst[n] = pd;
    }
#pragma unroll
    for (int off = 1; off <= 8; off <<= 1) {
#pragma unroll
        for (int n = 0; n < 8; n++) {
            src[n] += __shfl_xor_sync(0xffffffffu, src[n], off);
            dst[n] += __shfl_xor_sync(0xffffffffu, dst[n], off);
        }
    }
#pragma unroll
    for (int n = 0; n < 8; n++) {
        int row = m0 + ty * 8 + n;
        float e[8], mx = -1e30f;
#pragma unroll
        for (int m = 0; m < 8; m++) {
            float z = src[n] + dst[m];
            z = (z >= 0.f) ? z : 0.2f * z;
            e[m] = z;
            mx = fmaxf(mx, z);
        }
        float s = 0.f;
#pragma unroll
        for (int m = 0; m < 8; m++) { e[m] = __expf(e[m] - mx); s += e[m]; }
        float inv = __fdividef(1.f, s);
        float o[8];
#pragma unroll
        for (int j = 0; j < 8; j++) o[j] = b2v[j];
#pragma unroll
        for (int m = 0; m < 8; m++) {
            float w = e[m] * inv;
#pragma unroll
            for (int j = 0; j < 8; j++) o[j] += w * acc[m][j];
        }
        // write new h
        float4 h0v = make_float4(o[0], o[1], o[2], o[3]);
        float4 h1v = make_float4(o[4], o[5], o[6], o[7]);
        *reinterpret_cast<float4*>(&g_h[row * 128 + o0]) = h0v;
        *reinterpret_cast<float4*>(&g_h[row * 128 + o0 + 4]) = h1v;
        // output projection, reduced across the 16 tx lanes
        float p0 = 0.f, p1 = 0.f;
#pragma unroll
        for (int j = 0; j < 8; j++) { p0 += o[j] * wp0[j]; p1 += o[j] * wp1[j]; }
#pragma unroll
        for (int off = 1; off <= 8; off <<= 1) {
            p0 += __shfl_xor_sync(0xffffffffu, p0, off);
            p1 += __shfl_xor_sync(0xffffffffu, p1, off);
        }
        if (tx == 0) {
            out[(t * BN + row) * 2 + 0] = p0 + b_pos[0];
            out[(t * BN + row) * 2 + 1] = p1 + b_pos[1];
        }
    }
}

extern "C" void kernel_launch(void* const* d_in, const int* in_sizes, int n_in,
                              void* d_out, int out_size) {
    const float* action_real = (const float*)d_in[0];
    const float* h0          = (const float*)d_in[1];
    const float* pred_goal   = (const float*)d_in[2];
    // d_in[3] seq_start_end (uniform groups of 8 - unused)
    // d_in[4] teacher_forcing_ratio (unused, == 1)
    const float* W_emb  = (const float*)d_in[5];
    const float* b_emb  = (const float*)d_in[6];
    const float* W_ih   = (const float*)d_in[7];
    const float* W_hh   = (const float*)d_in[8];
    const float* b_ih   = (const float*)d_in[9];
    const float* b_hh   = (const float*)d_in[10];
    const float* W_goal = (const float*)d_in[11];
    const float* b_goal = (const float*)d_in[12];
    const float* w1     = (const float*)d_in[13];
    const float* a_src1 = (const float*)d_in[14];
    const float* a_dst1 = (const float*)d_in[15];
    const float* bias1  = (const float*)d_in[16];
    const float* w2     = (const float*)d_in[17];
    const float* a_src2 = (const float*)d_in[18];
    const float* a_dst2 = (const float*)d_in[19];
    const float* bias2  = (const float*)d_in[20];
    const float* W_pos  = (const float*)d_in[21];
    const float* b_pos  = (const float*)d_in[22];
    float* out = (float*)d_out;

    setup_kernel<<<256, 256>>>(W_emb, b_emb, W_ih, W_hh, b_ih, b_hh, w1);
    init_kernel<<<(BN * HN + 255) / 256, 256>>>(h0);
    gls_kernel<<<(PREDN * BN * 32 + 255) / 256, 256>>>(pred_goal, W_goal, b_goal);

    dim3 lgrid(4, 128);
    for (int t = 0; t < PREDN; t++) {
        lstm_kernel<<<lgrid, 256>>>(t, action_real, pred_goal, W_goal, b_goal);
        gat1_kernel<<<128, 256>>>(a_src1, a_dst1, bias1);
        gat2_kernel<<<128, 256>>>(t, w2, a_src2, a_dst2, bias2, W_pos, b_pos, out);
    }
}

// round 3
// speedup vs baseline: 1.1039x; 1.1039x over previous
#include <cuda_runtime.h>
#include <cuda_bf16.h>

#define BN 16384
#define HN 128
#define PREDN 12

// ---------------- device scratch ----------------
__device__ float g_Wp[128 * 512];   // permuted W_hh^T: Wp[k][n], n = unit*4 + gate
__device__ float g_Mc[2 * 512];     // folded x-path matrix (W_emb @ W_ih^T), permuted cols
__device__ float g_bv[512];         // folded bias (b_emb@W_ih^T + b_ih + b_hh), permuted
__device__ float g_W1[128 * 64];    // GAT layer1 weights K-major: W1[c][head*16+f]
__device__ float g_h[BN * HN];      // hidden state (GAT output / h0)
__device__ float g_c[BN * HN];      // LSTM cell state
__device__ float g_hpre[BN * HN];   // goal-gated LSTM h (input to GAT)
__device__ float g_gls[PREDN * BN]; // goal softmax log-denominator per (t,row)

__device__ __forceinline__ float fsig(float x) {
    return __fdividef(1.f, 1.f + __expf(-x));
}
__device__ __forceinline__ float ftanh(float x) {
    return __fdividef(2.f, 1.f + __expf(-2.f * x)) - 1.f;
}

// ---------------- setup: permutation + algebraic folding ----------------
__global__ void setup_kernel(const float* __restrict__ W_emb, const float* __restrict__ b_emb,
                             const float* __restrict__ W_ih, const float* __restrict__ W_hh,
                             const float* __restrict__ b_ih, const float* __restrict__ b_hh,
                             const float* __restrict__ w1) {
    int idx = blockIdx.x * 256 + threadIdx.x;   // 65536 threads
    if (idx < 128 * 512) {
        int k = idx >> 9, n = idx & 511;
        int u = n >> 2, g = n & 3;
        g_Wp[idx] = W_hh[(g * 128 + u) * 128 + k];
    }
    if (idx < 128 * 64) {
        int c = idx >> 6, kf = idx & 63;
        int hd = kf >> 4, f = kf & 15;
        g_W1[idx] = w1[(hd * 128 + c) * 16 + f];
    }
    if (idx < 512) {
        int n = idx;
        int u = n >> 2, g = n & 3;
        int row = g * 128 + u;
        float m0 = 0.f, m1 = 0.f, bb = 0.f;
        for (int e = 0; e < 64; e++) {
            float wih = W_ih[row * 64 + e];
            m0 += W_emb[e] * wih;
            m1 += W_emb[64 + e] * wih;
            bb += b_emb[e] * wih;
        }
        g_Mc[n] = m0;
        g_Mc[512 + n] = m1;
        g_bv[n] = bb + b_ih[row] + b_hh[row];
    }
}

__global__ void init_kernel(const float* __restrict__ h0) {
    int i = blockIdx.x * 256 + threadIdx.x;
    if (i < BN * HN) { g_h[i] = h0[i]; g_c[i] = 0.f; }
}

// one warp per (t,row): log-sum-exp of goal logits over 128 units
__global__ void gls_kernel(const float* __restrict__ pred_goal, const float* __restrict__ W_goal,
                           const float* __restrict__ b_goal) {
    int gw = (blockIdx.x * 256 + threadIdx.x) >> 5;
    int lane = threadIdx.x & 31;
    if (gw >= PREDN * BN) return;
    float pg0 = pred_goal[gw * 2 + 0], pg1 = pred_goal[gw * 2 + 1];
    float z[4];
    float m = -1e30f;
#pragma unroll
    for (int q = 0; q < 4; q++) {
        int u = lane + q * 32;
        z[q] = pg0 * W_goal[u] + pg1 * W_goal[128 + u] + b_goal[u];
        m = fmaxf(m, z[q]);
    }
#pragma unroll
    for (int s = 16; s > 0; s >>= 1) m = fmaxf(m, __shfl_xor_sync(0xffffffffu, m, s));
    float sum = 0.f;
#pragma unroll
    for (int q = 0; q < 4; q++) sum += __expf(z[q] - m);
#pragma unroll
    for (int s = 16; s > 0; s >>= 1) sum += __shfl_xor_sync(0xffffffffu, sum, s);
    if (lane == 0) g_gls[gw] = m + __logf(sum);
}

// ---------------- fused LSTM: h@Wp GEMM + cell update + goal gate ----------------
// launch_bounds(256,2): epilogue-only loads deferred past the K-loop to keep regs <=128
__global__ __launch_bounds__(256, 2) void lstm_kernel(int t,
                                                      const float* __restrict__ action_real,
                                                      const float* __restrict__ pred_goal,
                                                      const float* __restrict__ W_goal,
                                                      const float* __restrict__ b_goal) {
    __shared__ __align__(16) float As[32][132];
    __shared__ float4 Bs[32][32];
    __shared__ float arS[128][2];
    __shared__ float pgS[128][2];
    __shared__ float glsS[128];

    int tid = threadIdx.x;
    int tx = tid & 15, ty = tid >> 4;
    int m0 = blockIdx.y * 128;
    int n0 = blockIdx.x * 128;

    {
        int r = tid >> 1, cmp = tid & 1;
        arS[r][cmp] = action_real[(((8 + t) * BN) + m0 + r) * 2 + cmp];
        pgS[r][cmp] = pred_goal[((t * BN) + m0 + r) * 2 + cmp];
        if (tid < 128) glsS[tid] = g_gls[t * BN + m0 + tid];
    }

    float acc[8][8];
#pragma unroll
    for (int i = 0; i < 8; i++)
#pragma unroll
        for (int j = 0; j < 8; j++) acc[i][j] = 0.f;

    for (int kc = 0; kc < 4; kc++) {
        int k0 = kc * 32;
        __syncthreads();
#pragma unroll
        for (int it = 0; it < 4; it++) {
            int idx = it * 256 + tid;
            int r = idx >> 3, kq = idx & 7;
            float4 v = *reinterpret_cast<const float4*>(&g_h[(m0 + r) * 128 + k0 + kq * 4]);
            As[kq * 4 + 0][r] = v.x;
            As[kq * 4 + 1][r] = v.y;
            As[kq * 4 + 2][r] = v.z;
            As[kq * 4 + 3][r] = v.w;
        }
#pragma unroll
        for (int it = 0; it < 4; it++) {
            int idx = it * 256 + tid;
            int k = idx >> 5, nq = idx & 31;
            Bs[k][nq] = *reinterpret_cast<const float4*>(&g_Wp[(k0 + k) * 512 + n0 + nq * 4]);
        }
        __syncthreads();
#pragma unroll
        for (int k = 0; k < 32; k++) {
            float4 a0 = *reinterpret_cast<const float4*>(&As[k][ty * 8]);
            float4 a1 = *reinterpret_cast<const float4*>(&As[k][ty * 8 + 4]);
            float4 b0 = Bs[k][tx * 2], b1 = Bs[k][tx * 2 + 1];
            float av[8] = {a0.x, a0.y, a0.z, a0.w, a1.x, a1.y, a1.z, a1.w};
            float bw[8] = {b0.x, b0.y, b0.z, b0.w, b1.x, b1.y, b1.z, b1.w};
#pragma unroll
            for (int i = 0; i < 8; i++)
#pragma unroll
                for (int j = 0; j < 8; j++) acc[i][j] += av[i] * bw[j];
        }
    }
    __syncthreads();   // fence: keep epilogue loads out of the GEMM's live range

    // -------- epilogue-only constants (loaded AFTER the K-loop) --------
    int nb = n0 + tx * 8;
    float mc0[8], mc1[8], bvv[8];
#pragma unroll
    for (int j = 0; j < 8; j++) {
        mc0[j] = g_Mc[nb + j];
        mc1[j] = g_Mc[512 + nb + j];
        bvv[j] = g_bv[nb + j];
    }
    int u0 = (n0 >> 2) + 2 * tx;
    float wg0a = W_goal[u0], wg0b = W_goal[u0 + 1];
    float wg1a = W_goal[128 + u0], wg1b = W_goal[128 + u0 + 1];
    float bga = b_goal[u0], bgb = b_goal[u0 + 1];

    // epilogue: 2 units x 4 interleaved gates per thread, 8 rows
#pragma unroll
    for (int i = 0; i < 8; i++) {
        int rr = ty * 8 + i;
        int r = m0 + rr;
        float ar0 = arS[rr][0], ar1 = arS[rr][1];
        float pg0 = pgS[rr][0], pg1 = pgS[rr][1];
        float gls = glsS[rr];
        float2 cold = *reinterpret_cast<const float2*>(&g_c[r * 128 + u0]);
        float hv[2], cn[2];
#pragma unroll
        for (int p = 0; p < 2; p++) {
            int jb = p * 4;
            float gi = acc[i][jb + 0] + ar0 * mc0[jb + 0] + ar1 * mc1[jb + 0] + bvv[jb + 0];
            float gf = acc[i][jb + 1] + ar0 * mc0[jb + 1] + ar1 * mc1[jb + 1] + bvv[jb + 1];
            float gg = acc[i][jb + 2] + ar0 * mc0[jb + 2] + ar1 * mc1[jb + 2] + bvv[jb + 2];
            float go = acc[i][jb + 3] + ar0 * mc0[jb + 3] + ar1 * mc1[jb + 3] + bvv[jb + 3];
            float co = (p == 0) ? cold.x : cold.y;
            float cnv = fsig(gf) * co + fsig(gi) * ftanh(gg);
            float h1 = fsig(go) * ftanh(cnv);
            float z = (p == 0) ? (pg0 * wg0a + pg1 * wg1a + bga)
                               : (pg0 * wg0b + pg1 * wg1b + bgb);
            h1 *= __expf(z - gls);
            hv[p] = h1;
            cn[p] = cnv;
        }
        *reinterpret_cast<float2*>(&g_c[r * 128 + u0]) = make_float2(cn[0], cn[1]);
        *reinterpret_cast<float2*>(&g_hpre[r * 128 + u0]) = make_float2(hv[0], hv[1]);
    }
}

// ---------------- fused GAT (layer1 + layer2): hpre -> h, out ----------------
// Dynamic smem: As[32][132] | Bs[32][32] float4 | xS[128][68]
// 256 thr: tx=tid&15, ty=tid>>4; each (warp-quad) thread owns 8 rows = one group.
#define GAT_SMEM_FLOATS (32 * 132 + 32 * 32 * 4 + 128 * 68)
__global__ __launch_bounds__(256, 2) void gat_kernel(int t,
                                                     const float* __restrict__ a_src1,
                                                     const float* __restrict__ a_dst1,
                                                     const float* __restrict__ bias1,
                                                     const float* __restrict__ w2,
                                                     const float* __restrict__ a_src2,
                                                     const float* __restrict__ a_dst2,
                                                     const float* __restrict__ bias2,
                                                     const float* __restrict__ W_pos,
                                                     const float* __restrict__ b_pos,
                                                     float* __restrict__ out) {
    extern __shared__ __align__(16) float smem[];
    float (*As)[132] = reinterpret_cast<float(*)[132]>(smem);
    float4 (*Bs)[32] = reinterpret_cast<float4(*)[32]>(smem + 32 * 132);
    float (*xS)[68] = reinterpret_cast<float(*)[68]>(smem + 32 * 132 + 32 * 32 * 4);

    int tid = threadIdx.x;
    int tx = tid & 15, ty = tid >> 4;
    int m0 = blockIdx.x * 128;

    // ================= phase 1: hpre @ W1, attention heads, elu -> xS =================
    {
        float acc[8][4];
#pragma unroll
        for (int i = 0; i < 8; i++)
#pragma unroll
            for (int j = 0; j < 4; j++) acc[i][j] = 0.f;

        for (int kc = 0; kc < 4; kc++) {
            int k0 = kc * 32;
            __syncthreads();
#pragma unroll
            for (int it = 0; it < 4; it++) {
                int idx = it * 256 + tid;
                int r = idx >> 3, kq = idx & 7;
                float4 v = *reinterpret_cast<const float4*>(&g_hpre[(m0 + r) * 128 + k0 + kq * 4]);
                As[kq * 4 + 0][r] = v.x;
                As[kq * 4 + 1][r] = v.y;
                As[kq * 4 + 2][r] = v.z;
                As[kq * 4 + 3][r] = v.w;
            }
#pragma unroll
            for (int it = 0; it < 2; it++) {
                int idx = it * 256 + tid;
                int k = idx >> 4, q = idx & 15;
                Bs[k][q] = *reinterpret_cast<const float4*>(&g_W1[(k0 + k) * 64 + q * 4]);
            }
            __syncthreads();
#pragma unroll
            for (int k = 0; k < 32; k++) {
                float4 a0 = *reinterpret_cast<const float4*>(&As[k][ty * 8]);
                float4 a1 = *reinterpret_cast<const float4*>(&As[k][ty * 8 + 4]);
                float4 b = Bs[k][tx];
                float av[8] = {a0.x, a0.y, a0.z, a0.w, a1.x, a1.y, a1.z, a1.w};
                float bw[4] = {b.x, b.y, b.z, b.w};
#pragma unroll
                for (int i = 0; i < 8; i++)
#pragma unroll
                    for (int j = 0; j < 4; j++) acc[i][j] += av[i] * bw[j];
            }
        }

        int hd = tx >> 2;
        int fb = (tx & 3) * 4;
        float asv[4], adv[4], b1v[4];
#pragma unroll
        for (int j = 0; j < 4; j++) {
            asv[j] = a_src1[hd * 16 + fb + j];
            adv[j] = a_dst1[hd * 16 + fb + j];
            b1v[j] = bias1[fb + j];
        }

        float src[8], dst[8];
#pragma unroll
        for (int n = 0; n < 8; n++) {
            float ps = 0.f, pd = 0.f;
#pragma unroll
            for (int j = 0; j < 4; j++) { ps += acc[n][j] * asv[j]; pd += acc[n][j] * adv[j]; }
            src[n] = ps; dst[n] = pd;
        }
#pragma unroll
        for (int off = 1; off <= 2; off <<= 1) {
#pragma unroll
            for (int n = 0; n < 8; n++) {
                src[n] += __shfl_xor_sync(0xffffffffu, src[n], off);
                dst[n] += __shfl_xor_sync(0xffffffffu, dst[n], off);
            }
        }
        __syncthreads();   // As/Bs done; xS region safe to write
#pragma unroll
        for (int n = 0; n < 8; n++) {
            float e[8], mx = -1e30f;
#pragma unroll
            for (int m = 0; m < 8; m++) {
                float z = src[n] + dst[m];
                z = (z >= 0.f) ? z : 0.2f * z;
                e[m] = z;
                mx = fmaxf(mx, z);
            }
            float s = 0.f;
#pragma unroll
            for (int m = 0; m < 8; m++) { e[m] = __expf(e[m] - mx); s += e[m]; }
            float inv = __fdividef(1.f, s);
            float o[4] = {0.f, 0.f, 0.f, 0.f};
#pragma unroll
            for (int m = 0; m < 8; m++) {
                float w = e[m] * inv;
#pragma unroll
                for (int j = 0; j < 4; j++) o[j] += w * acc[m][j];
            }
            float4 xo;
            float* xp = &xo.x;
#pragma unroll
            for (int j = 0; j < 4; j++) {
                float v = o[j] + b1v[j];
                xp[j] = (v > 0.f) ? v : (__expf(v) - 1.f);
            }
            *reinterpret_cast<float4*>(&xS[ty * 8 + n][tx * 4]) = xo;
        }
    }
    __syncthreads();

    // ================= phase 2: xS @ w2, group attention, h + out =================
    {
        float acc[8][8];
#pragma unroll
        for (int i = 0; i < 8; i++)
#pragma unroll
            for (int j = 0; j < 8; j++) acc[i][j] = 0.f;

        for (int kc = 0; kc < 2; kc++) {
            int k0 = kc * 32;
            __syncthreads();
#pragma unroll
            for (int it = 0; it < 4; it++) {
                int idx = it * 256 + tid;
                int k = idx >> 5, q = idx & 31;
                Bs[k][q] = *reinterpret_cast<const float4*>(&w2[(k0 + k) * 128 + q * 4]);
            }
            __syncthreads();
#pragma unroll
            for (int kg = 0; kg < 8; kg++) {
                float a4[8][4];
#pragma unroll
                for (int i = 0; i < 8; i++) {
                    float4 v = *reinterpret_cast<const float4*>(&xS[ty * 8 + i][k0 + kg * 4]);
                    a4[i][0] = v.x; a4[i][1] = v.y; a4[i][2] = v.z; a4[i][3] = v.w;
                }
#pragma unroll
                for (int kk = 0; kk < 4; kk++) {
                    float4 b0 = Bs[kg * 4 + kk][tx * 2], b1 = Bs[kg * 4 + kk][tx * 2 + 1];
                    float bw[8] = {b0.x, b0.y, b0.z, b0.w, b1.x, b1.y, b1.z, b1.w};
#pragma unroll
                    for (int i = 0; i < 8; i++)
#pragma unroll
                        for (int j = 0; j < 8; j++) acc[i][j] += a4[i][kk] * bw[j];
                }
            }
        }

        int o0 = tx * 8;
        float asv[8], adv[8], b2v[8], wp0[8], wp1[8];
#pragma unroll
        for (int j = 0; j < 8; j++) {
            asv[j] = a_src2[o0 + j];
            adv[j] = a_dst2[o0 + j];
            b2v[j] = bias2[o0 + j];
            wp0[j] = W_pos[(o0 + j) * 2 + 0];
            wp1[j] = W_pos[(o0 + j) * 2 + 1];
        }

        float src[8], dst[8];
#pragma unroll
        for (int n = 0; n < 8; n++) {
            float ps = 0.f, pd = 0.f;
#pragma unroll
            for (int j = 0; j < 8; j++) { ps += acc[n][j] * asv[j]; pd += acc[n][j] * adv[j]; }
            src[n] = ps; dst[n] = pd;
        }
#pragma unroll
        for (int off = 1; off <= 8; off <<= 1) {
#pragma unroll
            for (int n = 0; n < 8; n++) {
                src[n] += __shfl_xor_sync(0xffffffffu, src[n], off);
                dst[n] += __shfl_xor_sync(0xffffffffu, dst[n], off);
            }
        }
#pragma unroll
        for (int n = 0; n < 8; n++) {
            int row = m0 + ty * 8 + n;
            float e[8], mx = -1e30f;
#pragma unroll
            for (int m = 0; m < 8; m++) {
                float z = src[n] + dst[m];
                z = (z >= 0.f) ? z : 0.2f * z;
                e[m] = z;
                mx = fmaxf(mx, z);
            }
            float s = 0.f;
#pragma unroll
            for (int m = 0; m < 8; m++) { e[m] = __expf(e[m] - mx); s += e[m]; }
            float inv = __fdividef(1.f, s);
            float o[8];
#pragma unroll
            for (int j = 0; j < 8; j++) o[j] = b2v[j];
#pragma unroll
            for (int m = 0; m < 8; m++) {
                float w = e[m] * inv;
#pragma unroll
                for (int j = 0; j < 8; j++) o[j] += w * acc[m][j];
            }
            *reinterpret_cast<float4*>(&g_h[row * 128 + o0]) = make_float4(o[0], o[1], o[2], o[3]);
            *reinterpret_cast<float4*>(&g_h[row * 128 + o0 + 4]) = make_float4(o[4], o[5], o[6], o[7]);
            float p0 = 0.f, p1 = 0.f;
#pragma unroll
            for (int j = 0; j < 8; j++) { p0 += o[j] * wp0[j]; p1 += o[j] * wp1[j]; }
#pragma unroll
            for (int off = 1; off <= 8; off <<= 1) {
                p0 += __shfl_xor_sync(0xffffffffu, p0, off);
                p1 += __shfl_xor_sync(0xffffffffu, p1, off);
            }
            if (tx == 0) {
                out[(t * BN + row) * 2 + 0] = p0 + b_pos[0];
                out[(t * BN + row) * 2 + 1] = p1 + b_pos[1];
            }
        }
    }
}

extern "C" void kernel_launch(void* const* d_in, const int* in_sizes, int n_in,
                              void* d_out, int out_size) {
    const float* action_real = (const float*)d_in[0];
    const float* h0          = (const float*)d_in[1];
    const float* pred_goal   = (const float*)d_in[2];
    // d_in[3] seq_start_end (uniform groups of 8 - unused)
    // d_in[4] teacher_forcing_ratio (unused, == 1)
    const float* W_emb  = (const float*)d_in[5];
    const float* b_emb  = (const float*)d_in[6];
    const float* W_ih   = (const float*)d_in[7];
    const float* W_hh   = (const float*)d_in[8];
    const float* b_ih   = (const float*)d_in[9];
    const float* b_hh   = (const float*)d_in[10];
    const float* W_goal = (const float*)d_in[11];
    const float* b_goal = (const float*)d_in[12];
    const float* w1     = (const float*)d_in[13];
    const float* a_src1 = (const float*)d_in[14];
    const float* a_dst1 = (const float*)d_in[15];
    const float* bias1  = (const float*)d_in[16];
    const float* w2     = (const float*)d_in[17];
    const float* a_src2 = (const float*)d_in[18];
    const float* a_dst2 = (const float*)d_in[19];
    const float* bias2  = (const float*)d_in[20];
    const float* W_pos  = (const float*)d_in[21];
    const float* b_pos  = (const float*)d_in[22];
    float* out = (float*)d_out;

    static int gat_smem_set = 0;
    (void)gat_smem_set;
    cudaFuncSetAttribute(gat_kernel, cudaFuncAttributeMaxDynamicSharedMemorySize,
                         GAT_SMEM_FLOATS * (int)sizeof(float));

    setup_kernel<<<256, 256>>>(W_emb, b_emb, W_ih, W_hh, b_ih, b_hh, w1);
    init_kernel<<<(BN * HN + 255) / 256, 256>>>(h0);
    gls_kernel<<<(PREDN * BN * 32 + 255) / 256, 256>>>(pred_goal, W_goal, b_goal);

    dim3 lgrid(4, 128);
    for (int t = 0; t < PREDN; t++) {
        lstm_kernel<<<lgrid, 256>>>(t, action_real, pred_goal, W_goal, b_goal);
        gat_kernel<<<128, 256, GAT_SMEM_FLOATS * sizeof(float)>>>(
            t, a_src1, a_dst1, bias1, w2, a_src2, a_dst2, bias2, W_pos, b_pos, out);
    }
}

// round 6
// speedup vs baseline: 1.2214x; 1.1064x over previous
#include <cuda_runtime.h>
#include <cuda_bf16.h>
#include <cstdint>

#define BN 16384
#define HN 128
#define PREDN 12

__device__ __forceinline__ uint32_t smem_u32(const void* p) {
    uint32_t a;
    asm("{ .reg .u64 t; cvta.to.shared.u64 t, %1; cvt.u32.u64 %0, t; }" : "=r"(a) : "l"(p));
    return a;
}

// blocked SW128 byte offset for [128 rows][128 bf16 cols] tile (8x64-bf16 atoms)
__device__ __forceinline__ int blk_off(int r, int c) {
    int boff = ((r >> 3) + (c >> 6) * 16) * 1024 + (r & 7) * 128 + (c & 63) * 2;
    return boff ^ ((boff >> 3) & 0x70);
}

__device__ __forceinline__ void ldsm4(uint32_t* r, uint32_t addr) {
    asm volatile("ldmatrix.sync.aligned.m8n8.x4.shared.b16 {%0,%1,%2,%3}, [%4];"
                 : "=r"(r[0]), "=r"(r[1]), "=r"(r[2]), "=r"(r[3]) : "r"(addr));
}
__device__ __forceinline__ void mma16816(float* c, const uint32_t* a, const uint32_t* b) {
    asm volatile(
        "mma.sync.aligned.m16n8k16.row.col.f32.bf16.bf16.f32 "
        "{%0,%1,%2,%3}, {%4,%5,%6,%7}, {%8,%9}, {%0,%1,%2,%3};"
        : "+f"(c[0]), "+f"(c[1]), "+f"(c[2]), "+f"(c[3])
        : "r"(a[0]), "r"(a[1]), "r"(a[2]), "r"(a[3]), "r"(b[0]), "r"(b[1]));
}

// ==================== device scratch ====================
__device__ __align__(16) unsigned short g_WpHi[4][16384]; // bf16 hi, [n 128][k 128] swizzled per chunk
__device__ __align__(16) unsigned short g_WpLo[4][16384]; // bf16 lo
__device__ float g_Mc[2 * 512];
__device__ float g_bv[512];
__device__ float g_W1[128 * 64];
__device__ float g_h[BN * HN];
__device__ float g_c[BN * HN];
__device__ float g_hpre[BN * HN];
__device__ float g_gls[PREDN * BN];

__device__ __forceinline__ float fsig(float x) { return __fdividef(1.f, 1.f + __expf(-x)); }
__device__ __forceinline__ float ftanh(float x) { return __fdividef(2.f, 1.f + __expf(-2.f * x)) - 1.f; }

// ==================== setup ====================
__global__ void setup_kernel(const float* __restrict__ W_emb, const float* __restrict__ b_emb,
                             const float* __restrict__ W_ih, const float* __restrict__ W_hh,
                             const float* __restrict__ b_ih, const float* __restrict__ b_hh,
                             const float* __restrict__ w1) {
    int idx = blockIdx.x * 256 + threadIdx.x;
    if (idx < 128 * 512) {
        int k = idx >> 9, n = idx & 511;       // n = unit*4 + gate (interleaved)
        int u = n >> 2, g = n & 3;
        float v = W_hh[(g * 128 + u) * 128 + k];
        __nv_bfloat16 bh = __float2bfloat16(v);
        __nv_bfloat16 bl = __float2bfloat16(v - __bfloat162float(bh));
        int chunk = n >> 7, nr = n & 127;
        int sw = blk_off(nr, k);               // B stored n-major: [n][k]
        g_WpHi[chunk][sw >> 1] = __bfloat16_as_ushort(bh);
        g_WpLo[chunk][sw >> 1] = __bfloat16_as_ushort(bl);
    }
    if (idx < 128 * 64) {
        int c = idx >> 6, kf = idx & 63;
        int hd = kf >> 4, f = kf & 15;
        g_W1[idx] = w1[(hd * 128 + c) * 16 + f];
    }
    if (idx < 512) {
        int n = idx;
        int u = n >> 2, g = n & 3;
        int row = g * 128 + u;
        float m0 = 0.f, m1 = 0.f, bb = 0.f;
        for (int e = 0; e < 64; e++) {
            float wih = W_ih[row * 64 + e];
            m0 += W_emb[e] * wih;
            m1 += W_emb[64 + e] * wih;
            bb += b_emb[e] * wih;
        }
        g_Mc[n] = m0;
        g_Mc[512 + n] = m1;
        g_bv[n] = bb + b_ih[row] + b_hh[row];
    }
}

__global__ void init_kernel(const float* __restrict__ h0) {
    int i = blockIdx.x * 256 + threadIdx.x;
    if (i < BN * HN) { g_h[i] = h0[i]; g_c[i] = 0.f; }
}

__global__ void gls_kernel(const float* __restrict__ pred_goal, const float* __restrict__ W_goal,
                           const float* __restrict__ b_goal) {
    int gw = (blockIdx.x * 256 + threadIdx.x) >> 5;
    int lane = threadIdx.x & 31;
    if (gw >= PREDN * BN) return;
    float pg0 = pred_goal[gw * 2 + 0], pg1 = pred_goal[gw * 2 + 1];
    float z[4];
    float m = -1e30f;
#pragma unroll
    for (int q = 0; q < 4; q++) {
        int u = lane + q * 32;
        z[q] = pg0 * W_goal[u] + pg1 * W_goal[128 + u] + b_goal[u];
        m = fmaxf(m, z[q]);
    }
#pragma unroll
    for (int s = 16; s > 0; s >>= 1) m = fmaxf(m, __shfl_xor_sync(0xffffffffu, m, s));
    float sum = 0.f;
#pragma unroll
    for (int q = 0; q < 4; q++) sum += __expf(z[q] - m);
#pragma unroll
    for (int s = 16; s > 0; s >>= 1) sum += __shfl_xor_sync(0xffffffffu, sum, s);
    if (lane == 0) g_gls[gw] = m + __logf(sum);
}

// ==================== LSTM via mma.sync bf16 split ====================
// smem: A_hi 32K | A_lo 32K | B_hi 32K | B_lo 32K
#define SM_AHI 0
#define SM_ALO 32768
#define SM_BHI 65536
#define SM_BLO 98304
#define LSTM_SMEM 131072

__global__ __launch_bounds__(256, 1) void lstm_mma(int t,
                                                   const float* __restrict__ action_real,
                                                   const float* __restrict__ pred_goal,
                                                   const float* __restrict__ W_goal,
                                                   const float* __restrict__ b_goal) {
    extern __shared__ __align__(1024) char sm[];
    uint32_t sb = smem_u32(sm);
    int tid = threadIdx.x;
    int w = tid >> 5, lane = tid & 31;
    int g = lane >> 2, q = lane & 3;
    int parity = q & 1, uloc = q >> 1;
    int wm = w >> 1, wn = w & 1;
    int m0 = blockIdx.x * 128;

    // ---- convert A = g_h[m0..m0+127][0..127] to bf16 hi/lo in swizzled smem ----
#pragma unroll
    for (int it = 0; it < 16; it++) {
        int idx = it * 256 + tid;
        int r = idx >> 5;
        int c4 = (idx & 31) * 4;
        float4 v = *reinterpret_cast<const float4*>(&g_h[(m0 + r) * 128 + c4]);
        float a[4] = {v.x, v.y, v.z, v.w};
        unsigned short hs[4], ls[4];
#pragma unroll
        for (int p = 0; p < 4; p++) {
            __nv_bfloat16 bh = __float2bfloat16(a[p]);
            __nv_bfloat16 bl = __float2bfloat16(a[p] - __bfloat162float(bh));
            hs[p] = __bfloat16_as_ushort(bh);
            ls[p] = __bfloat16_as_ushort(bl);
        }
        int sw = blk_off(r, c4);
        *reinterpret_cast<uint2*>(sm + SM_AHI + sw) =
            make_uint2((uint32_t)hs[0] | ((uint32_t)hs[1] << 16),
                       (uint32_t)hs[2] | ((uint32_t)hs[3] << 16));
        *reinterpret_cast<uint2*>(sm + SM_ALO + sw) =
            make_uint2((uint32_t)ls[0] | ((uint32_t)ls[1] << 16),
                       (uint32_t)ls[2] | ((uint32_t)ls[3] << 16));
    }

    // ---- per-row epilogue constants (2 rows per thread: mt=0,1) ----
    int rbase = m0 + wm * 32 + g + 8 * parity;
    float2 arr[2], pgr[2];
    float glr[2];
#pragma unroll
    for (int mt = 0; mt < 2; mt++) {
        int row = rbase + mt * 16;
        arr[mt] = *reinterpret_cast<const float2*>(&action_real[((8 + t) * BN + row) * 2]);
        pgr[mt] = *reinterpret_cast<const float2*>(&pred_goal[(t * BN + row) * 2]);
        glr[mt] = g_gls[t * BN + row];
    }

    // ldmatrix lane addressing (constant parts)
    int a_row = lane & 15;
    int a_khalf = (lane >> 4) * 8;
    int b_nloc = wn * 64 + (lane >> 4) * 8 + (lane & 7);
    int b_khalf = ((lane >> 3) & 1) * 8;

    for (int nc = 0; nc < 4; nc++) {
        __syncthreads();   // all warps done reading previous B chunk (and A convert, iter 0)
        {   // copy pre-swizzled B chunk (identity uint4 copy)
            const uint4* sH = reinterpret_cast<const uint4*>(g_WpHi[nc]);
            const uint4* sL = reinterpret_cast<const uint4*>(g_WpLo[nc]);
            uint4* dH = reinterpret_cast<uint4*>(sm + SM_BHI);
            uint4* dL = reinterpret_cast<uint4*>(sm + SM_BLO);
#pragma unroll
            for (int it = 0; it < 8; it++) {
                dH[it * 256 + tid] = sH[it * 256 + tid];
                dL[it * 256 + tid] = sL[it * 256 + tid];
            }
        }
        __syncthreads();

        float acc[2][8][4];
#pragma unroll
        for (int i = 0; i < 2; i++)
#pragma unroll
            for (int j = 0; j < 8; j++)
#pragma unroll
                for (int p = 0; p < 4; p++) acc[i][j][p] = 0.f;

#pragma unroll
        for (int ks = 0; ks < 8; ks++) {
            int kc = ks * 16;
            uint32_t ahi[2][4], alo[2][4];
#pragma unroll
            for (int mt = 0; mt < 2; mt++) {
                uint32_t ad = sb + SM_AHI + blk_off(wm * 32 + mt * 16 + a_row, kc + a_khalf);
                ldsm4(ahi[mt], ad);
                ldsm4(alo[mt], ad + 32768);
            }
            uint32_t bhi[4][4], blo[4][4];
#pragma unroll
            for (int pr = 0; pr < 4; pr++) {
                uint32_t bd = sb + SM_BHI + blk_off(b_nloc + pr * 16, kc + b_khalf);
                ldsm4(bhi[pr], bd);
                ldsm4(blo[pr], bd + 32768);
            }
#pragma unroll
            for (int mt = 0; mt < 2; mt++)
#pragma unroll
                for (int nt = 0; nt < 8; nt++) {
                    int pr = nt >> 1, hf = (nt & 1) * 2;
                    mma16816(acc[mt][nt], ahi[mt], &bhi[pr][hf]);
                    mma16816(acc[mt][nt], ahi[mt], &blo[pr][hf]);
                    mma16816(acc[mt][nt], alo[mt], &bhi[pr][hf]);
                }
        }

        // ---- epilogue: pair-exchange gates, LSTM cell + goal gate ----
#pragma unroll
        for (int nt = 0; nt < 8; nt++) {
            int u = nc * 32 + wn * 16 + nt * 2 + uloc;
            int n4 = u * 4;
            float4 mA = *reinterpret_cast<const float4*>(&g_Mc[n4]);
            float4 mB = *reinterpret_cast<const float4*>(&g_Mc[512 + n4]);
            float4 bv = *reinterpret_cast<const float4*>(&g_bv[n4]);
            float wga = W_goal[u], wgb = W_goal[128 + u], bgu = b_goal[u];
#pragma unroll
            for (int mt = 0; mt < 2; mt++) {
                float c0 = acc[mt][nt][0], c1 = acc[mt][nt][1];
                float c2 = acc[mt][nt][2], c3 = acc[mt][nt][3];
                float xa = __shfl_xor_sync(0xffffffffu, parity ? c0 : c2, 1);
                float xb = __shfl_xor_sync(0xffffffffu, parity ? c1 : c3, 1);
                float gi, gf, gg2, go;
                if (parity == 0) { gi = c0; gf = c1; gg2 = xa; go = xb; }
                else             { gi = xa; gf = xb; gg2 = c2; go = c3; }
                int row = rbase + mt * 16;
                float ar0 = arr[mt].x, ar1 = arr[mt].y;
                gi += ar0 * mA.x + ar1 * mB.x + bv.x;
                gf += ar0 * mA.y + ar1 * mB.y + bv.y;
                gg2 += ar0 * mA.z + ar1 * mB.z + bv.z;
                go += ar0 * mA.w + ar1 * mB.w + bv.w;
                float cold = g_c[row * 128 + u];
                float cn = fsig(gf) * cold + fsig(gi) * ftanh(gg2);
                float hh = fsig(go) * ftanh(cn);
                float z = pgr[mt].x * wga + pgr[mt].y * wgb + bgu;
                hh *= __expf(z - glr[mt]);
                g_c[row * 128 + u] = cn;
                g_hpre[row * 128 + u] = hh;
            }
        }
    }
}

// ==================== fused GAT (unchanged from R3) ====================
#define GAT_SMEM_FLOATS (32 * 132 + 32 * 32 * 4 + 128 * 68)
__global__ __launch_bounds__(256, 2) void gat_kernel(int t,
                                                     const float* __restrict__ a_src1,
                                                     const float* __restrict__ a_dst1,
                                                     const float* __restrict__ bias1,
                                                     const float* __restrict__ w2,
                                                     const float* __restrict__ a_src2,
                                                     const float* __restrict__ a_dst2,
                                                     const float* __restrict__ bias2,
                                                     const float* __restrict__ W_pos,
                                                     const float* __restrict__ b_pos,
                                                     float* __restrict__ out) {
    extern __shared__ __align__(16) float smem[];
    float (*As)[132] = reinterpret_cast<float(*)[132]>(smem);
    float4 (*Bs)[32] = reinterpret_cast<float4(*)[32]>(smem + 32 * 132);
    float (*xS)[68] = reinterpret_cast<float(*)[68]>(smem + 32 * 132 + 32 * 32 * 4);

    int tid = threadIdx.x;
    int tx = tid & 15, ty = tid >> 4;
    int m0 = blockIdx.x * 128;

    {   // phase 1: hpre @ W1 + heads attention + elu -> xS
        float acc[8][4];
#pragma unroll
        for (int i = 0; i < 8; i++)
#pragma unroll
            for (int j = 0; j < 4; j++) acc[i][j] = 0.f;

        for (int kc = 0; kc < 4; kc++) {
            int k0 = kc * 32;
            __syncthreads();
#pragma unroll
            for (int it = 0; it < 4; it++) {
                int idx = it * 256 + tid;
                int r = idx >> 3, kq = idx & 7;
                float4 v = *reinterpret_cast<const float4*>(&g_hpre[(m0 + r) * 128 + k0 + kq * 4]);
                As[kq * 4 + 0][r] = v.x;
                As[kq * 4 + 1][r] = v.y;
                As[kq * 4 + 2][r] = v.z;
                As[kq * 4 + 3][r] = v.w;
            }
#pragma unroll
            for (int it = 0; it < 2; it++) {
                int idx = it * 256 + tid;
                int k = idx >> 4, q = idx & 15;
                Bs[k][q] = *reinterpret_cast<const float4*>(&g_W1[(k0 + k) * 64 + q * 4]);
            }
            __syncthreads();
#pragma unroll
            for (int k = 0; k < 32; k++) {
                float4 a0 = *reinterpret_cast<const float4*>(&As[k][ty * 8]);
                float4 a1 = *reinterpret_cast<const float4*>(&As[k][ty * 8 + 4]);
                float4 b = Bs[k][tx];
                float av[8] = {a0.x, a0.y, a0.z, a0.w, a1.x, a1.y, a1.z, a1.w};
                float bw[4] = {b.x, b.y, b.z, b.w};
#pragma unroll
                for (int i = 0; i < 8; i++)
#pragma unroll
                    for (int j = 0; j < 4; j++) acc[i][j] += av[i] * bw[j];
            }
        }

        int hd = tx >> 2;
        int fb = (tx & 3) * 4;
        float asv[4], adv[4], b1v[4];
#pragma unroll
        for (int j = 0; j < 4; j++) {
            asv[j] = a_src1[hd * 16 + fb + j];
            adv[j] = a_dst1[hd * 16 + fb + j];
            b1v[j] = bias1[fb + j];
        }

        float src[8], dst[8];
#pragma unroll
        for (int n = 0; n < 8; n++) {
            float ps = 0.f, pd = 0.f;
#pragma unroll
            for (int j = 0; j < 4; j++) { ps += acc[n][j] * asv[j]; pd += acc[n][j] * adv[j]; }
            src[n] = ps; dst[n] = pd;
        }
#pragma unroll
        for (int off = 1; off <= 2; off <<= 1) {
#pragma unroll
            for (int n = 0; n < 8; n++) {
                src[n] += __shfl_xor_sync(0xffffffffu, src[n], off);
                dst[n] += __shfl_xor_sync(0xffffffffu, dst[n], off);
            }
        }
        __syncthreads();
#pragma unroll
        for (int n = 0; n < 8; n++) {
            float e[8], mx = -1e30f;
#pragma unroll
            for (int m = 0; m < 8; m++) {
                float z = src[n] + dst[m];
                z = (z >= 0.f) ? z : 0.2f * z;
                e[m] = z;
                mx = fmaxf(mx, z);
            }
            float s = 0.f;
#pragma unroll
            for (int m = 0; m < 8; m++) { e[m] = __expf(e[m] - mx); s += e[m]; }
            float inv = __fdividef(1.f, s);
            float o[4] = {0.f, 0.f, 0.f, 0.f};
#pragma unroll
            for (int m = 0; m < 8; m++) {
                float w = e[m] * inv;
#pragma unroll
                for (int j = 0; j < 4; j++) o[j] += w * acc[m][j];
            }
            float4 xo;
            float* xp = &xo.x;
#pragma unroll
            for (int j = 0; j < 4; j++) {
                float v = o[j] + b1v[j];
                xp[j] = (v > 0.f) ? v : (__expf(v) - 1.f);
            }
            *reinterpret_cast<float4*>(&xS[ty * 8 + n][tx * 4]) = xo;
        }
    }
    __syncthreads();

    {   // phase 2: xS @ w2 + group attention + h/out
        float acc[8][8];
#pragma unroll
        for (int i = 0; i < 8; i++)
#pragma unroll
            for (int j = 0; j < 8; j++) acc[i][j] = 0.f;

        for (int kc = 0; kc < 2; kc++) {
            int k0 = kc * 32;
            __syncthreads();
#pragma unroll
            for (int it = 0; it < 4; it++) {
                int idx = it * 256 + tid;
                int k = idx >> 5, q = idx & 31;
                Bs[k][q] = *reinterpret_cast<const float4*>(&w2[(k0 + k) * 128 + q * 4]);
            }
            __syncthreads();
#pragma unroll
            for (int kg = 0; kg < 8; kg++) {
                float a4[8][4];
#pragma unroll
                for (int i = 0; i < 8; i++) {
                    float4 v = *reinterpret_cast<const float4*>(&xS[ty * 8 + i][k0 + kg * 4]);
                    a4[i][0] = v.x; a4[i][1] = v.y; a4[i][2] = v.z; a4[i][3] = v.w;
                }
#pragma unroll
                for (int kk = 0; kk < 4; kk++) {
                    float4 b0 = Bs[kg * 4 + kk][tx * 2], b1 = Bs[kg * 4 + kk][tx * 2 + 1];
                    float bw[8] = {b0.x, b0.y, b0.z, b0.w, b1.x, b1.y, b1.z, b1.w};
#pragma unroll
                    for (int i = 0; i < 8; i++)
#pragma unroll
                        for (int j = 0; j < 8; j++) acc[i][j] += a4[i][kk] * bw[j];
                }
            }
        }

        int o0 = tx * 8;
        float asv[8], adv[8], b2v[8], wp0[8], wp1[8];
#pragma unroll
        for (int j = 0; j < 8; j++) {
            asv[j] = a_src2[o0 + j];
            adv[j] = a_dst2[o0 + j];
            b2v[j] = bias2[o0 + j];
            wp0[j] = W_pos[(o0 + j) * 2 + 0];
            wp1[j] = W_pos[(o0 + j) * 2 + 1];
        }

        float src[8], dst[8];
#pragma unroll
        for (int n = 0; n < 8; n++) {
            float ps = 0.f, pd = 0.f;
#pragma unroll
            for (int j = 0; j < 8; j++) { ps += acc[n][j] * asv[j]; pd += acc[n][j] * adv[j]; }
            src[n] = ps; dst[n] = pd;
        }
#pragma unroll
        for (int off = 1; off <= 8; off <<= 1) {
#pragma unroll
            for (int n = 0; n < 8; n++) {
                src[n] += __shfl_xor_sync(0xffffffffu, src[n], off);
                dst[n] += __shfl_xor_sync(0xffffffffu, dst[n], off);
            }
        }
#pragma unroll
        for (int n = 0; n < 8; n++) {
            int row = m0 + ty * 8 + n;
            float e[8], mx = -1e30f;
#pragma unroll
            for (int m = 0; m < 8; m++) {
                float z = src[n] + dst[m];
                z = (z >= 0.f) ? z : 0.2f * z;
                e[m] = z;
                mx = fmaxf(mx, z);
            }
            float s = 0.f;
#pragma unroll
            for (int m = 0; m < 8; m++) { e[m] = __expf(e[m] - mx); s += e[m]; }
            float inv = __fdividef(1.f, s);
            float o[8];
#pragma unroll
            for (int j = 0; j < 8; j++) o[j] = b2v[j];
#pragma unroll
            for (int m = 0; m < 8; m++) {
                float w = e[m] * inv;
#pragma unroll
                for (int j = 0; j < 8; j++) o[j] += w * acc[m][j];
            }
            *reinterpret_cast<float4*>(&g_h[row * 128 + o0]) = make_float4(o[0], o[1], o[2], o[3]);
            *reinterpret_cast<float4*>(&g_h[row * 128 + o0 + 4]) = make_float4(o[4], o[5], o[6], o[7]);
            float p0 = 0.f, p1 = 0.f;
#pragma unroll
            for (int j = 0; j < 8; j++) { p0 += o[j] * wp0[j]; p1 += o[j] * wp1[j]; }
#pragma unroll
            for (int off = 1; off <= 8; off <<= 1) {
                p0 += __shfl_xor_sync(0xffffffffu, p0, off);
                p1 += __shfl_xor_sync(0xffffffffu, p1, off);
            }
            if (tx == 0) {
                out[(t * BN + row) * 2 + 0] = p0 + b_pos[0];
                out[(t * BN + row) * 2 + 1] = p1 + b_pos[1];
            }
        }
    }
}

extern "C" void kernel_launch(void* const* d_in, const int* in_sizes, int n_in,
                              void* d_out, int out_size) {
    const float* action_real = (const float*)d_in[0];
    const float* h0          = (const float*)d_in[1];
    const float* pred_goal   = (const float*)d_in[2];
    const float* W_emb  = (const float*)d_in[5];
    const float* b_emb  = (const float*)d_in[6];
    const float* W_ih   = (const float*)d_in[7];
    const float* W_hh   = (const float*)d_in[8];
    const float* b_ih   = (const float*)d_in[9];
    const float* b_hh   = (const float*)d_in[10];
    const float* W_goal = (const float*)d_in[11];
    const float* b_goal = (const float*)d_in[12];
    const float* w1     = (const float*)d_in[13];
    const float* a_src1 = (const float*)d_in[14];
    const float* a_dst1 = (const float*)d_in[15];
    const float* bias1  = (const float*)d_in[16];
    const float* w2     = (const float*)d_in[17];
    const float* a_src2 = (const float*)d_in[18];
    const float* a_dst2 = (const float*)d_in[19];
    const float* bias2  = (const float*)d_in[20];
    const float* W_pos  = (const float*)d_in[21];
    const float* b_pos  = (const float*)d_in[22];
    float* out = (float*)d_out;

    cudaFuncSetAttribute(gat_kernel, cudaFuncAttributeMaxDynamicSharedMemorySize,
                         GAT_SMEM_FLOATS * (int)sizeof(float));
    cudaFuncSetAttribute(lstm_mma, cudaFuncAttributeMaxDynamicSharedMemorySize, LSTM_SMEM);

    setup_kernel<<<256, 256>>>(W_emb, b_emb, W_ih, W_hh, b_ih, b_hh, w1);
    init_kernel<<<(BN * HN + 255) / 256, 256>>>(h0);
    gls_kernel<<<(PREDN * BN * 32 + 255) / 256, 256>>>(pred_goal, W_goal, b_goal);

    for (int t = 0; t < PREDN; t++) {
        lstm_mma<<<128, 256, LSTM_SMEM>>>(t, action_real, pred_goal, W_goal, b_goal);
        gat_kernel<<<128, 256, GAT_SMEM_FLOATS * sizeof(float)>>>(
            t, a_src1, a_dst1, bias1, w2, a_src2, a_dst2, bias2, W_pos, b_pos, out);
    }
}

// round 7
// speedup vs baseline: 1.2746x; 1.0436x over previous
#include <cuda_runtime.h>
#include <cuda_bf16.h>
#include <cstdint>

#define BN 16384
#define HN 128
#define PREDN 12

__device__ __forceinline__ uint32_t smem_u32(const void* p) {
    uint32_t a;
    asm("{ .reg .u64 t; cvta.to.shared.u64 t, %1; cvt.u32.u64 %0, t; }" : "=r"(a) : "l"(p));
    return a;
}

// blocked SW128 byte offset for [128 rows][128 bf16 cols] tile (8x64-bf16 atoms)
__device__ __forceinline__ int blk_off(int r, int c) {
    int boff = ((r >> 3) + (c >> 6) * 16) * 1024 + (r & 7) * 128 + (c & 63) * 2;
    return boff ^ ((boff >> 3) & 0x70);
}

__device__ __forceinline__ void ldsm4(uint32_t* r, uint32_t addr) {
    asm volatile("ldmatrix.sync.aligned.m8n8.x4.shared.b16 {%0,%1,%2,%3}, [%4];"
                 : "=r"(r[0]), "=r"(r[1]), "=r"(r[2]), "=r"(r[3]) : "r"(addr));
}
__device__ __forceinline__ void mma16816(float* c, const uint32_t* a, const uint32_t* b) {
    asm volatile(
        "mma.sync.aligned.m16n8k16.row.col.f32.bf16.bf16.f32 "
        "{%0,%1,%2,%3}, {%4,%5,%6,%7}, {%8,%9}, {%0,%1,%2,%3};"
        : "+f"(c[0]), "+f"(c[1]), "+f"(c[2]), "+f"(c[3])
        : "r"(a[0]), "r"(a[1]), "r"(a[2]), "r"(a[3]), "r"(b[0]), "r"(b[1]));
}
#define CP_ASYNC16(dst, src) \
    asm volatile("cp.async.cg.shared.global [%0], [%1], 16;" :: "r"(dst), "l"(src))
#define CP_COMMIT asm volatile("cp.async.commit_group;" ::: "memory")
#define CP_WAIT1 asm volatile("cp.async.wait_group 1;" ::: "memory")
#define CP_WAIT0 asm volatile("cp.async.wait_group 0;" ::: "memory")

// ==================== device scratch ====================
__device__ __align__(16) unsigned short g_WpHi[4][16384]; // bf16 hi, [n 128][k 128] swizzled per chunk
__device__ __align__(16) unsigned short g_WpLo[4][16384]; // bf16 lo
__device__ float g_Mc[2 * 512];
__device__ float g_bv[512];
__device__ float g_W1[128 * 64];
__device__ float g_h[BN * HN];
__device__ float g_c[BN * HN];
__device__ float g_hpre[BN * HN];
__device__ float g_gls[PREDN * BN];

__device__ __forceinline__ float fsig(float x) { return __fdividef(1.f, 1.f + __expf(-x)); }
__device__ __forceinline__ float ftanh(float x) { return __fdividef(2.f, 1.f + __expf(-2.f * x)) - 1.f; }

// ==================== setup ====================
__global__ void setup_kernel(const float* __restrict__ W_emb, const float* __restrict__ b_emb,
                             const float* __restrict__ W_ih, const float* __restrict__ W_hh,
                             const float* __restrict__ b_ih, const float* __restrict__ b_hh,
                             const float* __restrict__ w1) {
    int idx = blockIdx.x * 256 + threadIdx.x;
    if (idx < 128 * 512) {
        int k = idx >> 9, n = idx & 511;       // n = unit*4 + gate (interleaved)
        int u = n >> 2, g = n & 3;
        float v = W_hh[(g * 128 + u) * 128 + k];
        __nv_bfloat16 bh = __float2bfloat16(v);
        __nv_bfloat16 bl = __float2bfloat16(v - __bfloat162float(bh));
        int chunk = n >> 7, nr = n & 127;
        int sw = blk_off(nr, k);               // B stored n-major: [n][k]
        g_WpHi[chunk][sw >> 1] = __bfloat16_as_ushort(bh);
        g_WpLo[chunk][sw >> 1] = __bfloat16_as_ushort(bl);
    }
    if (idx < 128 * 64) {
        int c = idx >> 6, kf = idx & 63;
        int hd = kf >> 4, f = kf & 15;
        g_W1[idx] = w1[(hd * 128 + c) * 16 + f];
    }
    if (idx < 512) {
        int n = idx;
        int u = n >> 2, g = n & 3;
        int row = g * 128 + u;
        float m0 = 0.f, m1 = 0.f, bb = 0.f;
        for (int e = 0; e < 64; e++) {
            float wih = W_ih[row * 64 + e];
            m0 += W_emb[e] * wih;
            m1 += W_emb[64 + e] * wih;
            bb += b_emb[e] * wih;
        }
        g_Mc[n] = m0;
        g_Mc[512 + n] = m1;
        g_bv[n] = bb + b_ih[row] + b_hh[row];
    }
}

__global__ void init_kernel(const float* __restrict__ h0) {
    int i = blockIdx.x * 256 + threadIdx.x;
    if (i < BN * HN) { g_h[i] = h0[i]; g_c[i] = 0.f; }
}

__global__ void gls_kernel(const float* __restrict__ pred_goal, const float* __restrict__ W_goal,
                           const float* __restrict__ b_goal) {
    int gw = (blockIdx.x * 256 + threadIdx.x) >> 5;
    int lane = threadIdx.x & 31;
    if (gw >= PREDN * BN) return;
    float pg0 = pred_goal[gw * 2 + 0], pg1 = pred_goal[gw * 2 + 1];
    float z[4];
    float m = -1e30f;
#pragma unroll
    for (int q = 0; q < 4; q++) {
        int u = lane + q * 32;
        z[q] = pg0 * W_goal[u] + pg1 * W_goal[128 + u] + b_goal[u];
        m = fmaxf(m, z[q]);
    }
#pragma unroll
    for (int s = 16; s > 0; s >>= 1) m = fmaxf(m, __shfl_xor_sync(0xffffffffu, m, s));
    float sum = 0.f;
#pragma unroll
    for (int q = 0; q < 4; q++) sum += __expf(z[q] - m);
#pragma unroll
    for (int s = 16; s > 0; s >>= 1) sum += __shfl_xor_sync(0xffffffffu, sum, s);
    if (lane == 0) g_gls[gw] = m + __logf(sum);
}

// ==================== LSTM via mma.sync bf16 split, 512 thr + cp.async ====================
// smem: A_hi 32K | A_lo 32K | Bbuf0 (hi32K+lo32K) | Bbuf1 (hi32K+lo32K) = 192KB
#define SM_AHI 0
#define SM_ALO 32768
#define SM_B0  65536
#define LSTM_SMEM 196608

__global__ __launch_bounds__(512, 1) void lstm_mma(int t,
                                                   const float* __restrict__ action_real,
                                                   const float* __restrict__ pred_goal,
                                                   const float* __restrict__ W_goal,
                                                   const float* __restrict__ b_goal) {
    extern __shared__ __align__(1024) char sm[];
    uint32_t sb = smem_u32(sm);
    int tid = threadIdx.x;
    int w = tid >> 5, lane = tid & 31;
    int g = lane >> 2, q = lane & 3;
    int parity = q & 1, uloc = q >> 1;
    int wm = w >> 1, wn = w & 1;     // 8 m16 tiles x 2 n64 halves
    int m0 = blockIdx.x * 128;

    // ---- prefetch B chunk 0 into buf0 ----
    {
        const char* srcH = (const char*)g_WpHi[0];
        const char* srcL = (const char*)g_WpLo[0];
        uint32_t dH = sb + SM_B0;
        uint32_t dL = dH + 32768;
#pragma unroll
        for (int it = 0; it < 4; it++) {
            int off = (it * 512 + tid) * 16;
            CP_ASYNC16(dH + off, srcH + off);
            CP_ASYNC16(dL + off, srcL + off);
        }
        CP_COMMIT;
    }

    // ---- convert A = g_h[m0..m0+127][:] to bf16 hi/lo swizzled (overlaps cp.async) ----
#pragma unroll
    for (int it = 0; it < 8; it++) {
        int idx = it * 512 + tid;
        int r = idx >> 5;
        int c4 = (idx & 31) * 4;
        float4 v = *reinterpret_cast<const float4*>(&g_h[(m0 + r) * 128 + c4]);
        float a[4] = {v.x, v.y, v.z, v.w};
        unsigned short hs[4], ls[4];
#pragma unroll
        for (int p = 0; p < 4; p++) {
            __nv_bfloat16 bh = __float2bfloat16(a[p]);
            __nv_bfloat16 bl = __float2bfloat16(a[p] - __bfloat162float(bh));
            hs[p] = __bfloat16_as_ushort(bh);
            ls[p] = __bfloat16_as_ushort(bl);
        }
        int sw = blk_off(r, c4);
        *reinterpret_cast<uint2*>(sm + SM_AHI + sw) =
            make_uint2((uint32_t)hs[0] | ((uint32_t)hs[1] << 16),
                       (uint32_t)hs[2] | ((uint32_t)hs[3] << 16));
        *reinterpret_cast<uint2*>(sm + SM_ALO + sw) =
            make_uint2((uint32_t)ls[0] | ((uint32_t)ls[1] << 16),
                       (uint32_t)ls[2] | ((uint32_t)ls[3] << 16));
    }

    // ---- per-row epilogue constants (rows rg and rg+8) ----
    int rg = m0 + wm * 16 + g;
    float2 arr[2], pgr[2];
    float glr[2];
#pragma unroll
    for (int mt = 0; mt < 2; mt++) {
        int row = rg + mt * 8;
        arr[mt] = *reinterpret_cast<const float2*>(&action_real[((8 + t) * BN + row) * 2]);
        pgr[mt] = *reinterpret_cast<const float2*>(&pred_goal[(t * BN + row) * 2]);
        glr[mt] = g_gls[t * BN + row];
    }

    int a_row = lane & 15;
    int a_khalf = (lane >> 4) * 8;
    int b_nloc = wn * 64 + (lane >> 4) * 8 + (lane & 7);
    int b_khalf = ((lane >> 3) & 1) * 8;

    for (int nc = 0; nc < 4; nc++) {
        uint32_t bbase = sb + SM_B0 + (nc & 1) * 65536;
        if (nc < 3) {   // prefetch next chunk into other buf (safe: freed by prev end-sync)
            const char* srcH = (const char*)g_WpHi[nc + 1];
            const char* srcL = (const char*)g_WpLo[nc + 1];
            uint32_t dH = sb + SM_B0 + (((nc + 1) & 1) * 65536);
            uint32_t dL = dH + 32768;
#pragma unroll
            for (int it = 0; it < 4; it++) {
                int off = (it * 512 + tid) * 16;
                CP_ASYNC16(dH + off, srcH + off);
                CP_ASYNC16(dL + off, srcL + off);
            }
            CP_COMMIT;
            CP_WAIT1;
        } else {
            CP_WAIT0;
        }
        __syncthreads();   // chunk nc visible to all warps (covers A convert on nc=0)

        float acc[8][4];
#pragma unroll
        for (int j = 0; j < 8; j++)
#pragma unroll
            for (int p = 0; p < 4; p++) acc[j][p] = 0.f;

#pragma unroll
        for (int ks = 0; ks < 8; ks++) {
            int kc = ks * 16;
            uint32_t ahi[4], alo[4];
            uint32_t ad = sb + SM_AHI + blk_off(wm * 16 + a_row, kc + a_khalf);
            ldsm4(ahi, ad);
            ldsm4(alo, ad + 32768);
            uint32_t bhi[4][4], blo[4][4];
#pragma unroll
            for (int pr = 0; pr < 4; pr++) {
                uint32_t bd = bbase + blk_off(b_nloc + pr * 16, kc + b_khalf);
                ldsm4(bhi[pr], bd);
                ldsm4(blo[pr], bd + 32768);
            }
#pragma unroll
            for (int nt = 0; nt < 8; nt++) {
                int pr = nt >> 1, hf = (nt & 1) * 2;
                mma16816(acc[nt], ahi, &bhi[pr][hf]);
                mma16816(acc[nt], ahi, &blo[pr][hf]);
                mma16816(acc[nt], alo, &bhi[pr][hf]);
            }
        }

        // ---- epilogue: pair-exchange gates, LSTM cell + goal gate (rows rg, rg+8) ----
#pragma unroll
        for (int nt = 0; nt < 8; nt++) {
            int u = nc * 32 + wn * 16 + nt * 2 + uloc;
            int n4 = u * 4;
            float4 mA = *reinterpret_cast<const float4*>(&g_Mc[n4]);
            float4 mB = *reinterpret_cast<const float4*>(&g_Mc[512 + n4]);
            float4 bv = *reinterpret_cast<const float4*>(&g_bv[n4]);
            float wga = W_goal[u], wgb = W_goal[128 + u], bgu = b_goal[u];
            float c0 = acc[nt][0], c1 = acc[nt][1], c2 = acc[nt][2], c3 = acc[nt][3];
            float x0 = __shfl_xor_sync(0xffffffffu, c0, 1);
            float x1 = __shfl_xor_sync(0xffffffffu, c1, 1);
            float x2 = __shfl_xor_sync(0xffffffffu, c2, 1);
            float x3 = __shfl_xor_sync(0xffffffffu, c3, 1);
#pragma unroll
            for (int mt = 0; mt < 2; mt++) {
                float gi, gf, gg2, go;
                if (parity == 0) {
                    gi = (mt == 0) ? c0 : c2; gf = (mt == 0) ? c1 : c3;
                    gg2 = (mt == 0) ? x0 : x2; go = (mt == 0) ? x1 : x3;
                } else {
                    gi = (mt == 0) ? x0 : x2; gf = (mt == 0) ? x1 : x3;
                    gg2 = (mt == 0) ? c0 : c2; go = (mt == 0) ? c1 : c3;
                }
                int row = rg + mt * 8;
                float ar0 = arr[mt].x, ar1 = arr[mt].y;
                gi += ar0 * mA.x + ar1 * mB.x + bv.x;
                gf += ar0 * mA.y + ar1 * mB.y + bv.y;
                gg2 += ar0 * mA.z + ar1 * mB.z + bv.z;
                go += ar0 * mA.w + ar1 * mB.w + bv.w;
                float cold = g_c[row * 128 + u];
                float cn = fsig(gf) * cold + fsig(gi) * ftanh(gg2);
                float hh = fsig(go) * ftanh(cn);
                float z = pgr[mt].x * wga + pgr[mt].y * wgb + bgu;
                hh *= __expf(z - glr[mt]);
                g_c[row * 128 + u] = cn;
                g_hpre[row * 128 + u] = hh;
            }
        }
        __syncthreads();   // all warps done with buf nc&1 before it's overwritten
    }
}

// ==================== fused GAT (unchanged) ====================
#define GAT_SMEM_FLOATS (32 * 132 + 32 * 32 * 4 + 128 * 68)
__global__ __launch_bounds__(256, 2) void gat_kernel(int t,
                                                     const float* __restrict__ a_src1,
                                                     const float* __restrict__ a_dst1,
                                                     const float* __restrict__ bias1,
                                                     const float* __restrict__ w2,
                                                     const float* __restrict__ a_src2,
                                                     const float* __restrict__ a_dst2,
                                                     const float* __restrict__ bias2,
                                                     const float* __restrict__ W_pos,
                                                     const float* __restrict__ b_pos,
                                                     float* __restrict__ out) {
    extern __shared__ __align__(16) float smem[];
    float (*As)[132] = reinterpret_cast<float(*)[132]>(smem);
    float4 (*Bs)[32] = reinterpret_cast<float4(*)[32]>(smem + 32 * 132);
    float (*xS)[68] = reinterpret_cast<float(*)[68]>(smem + 32 * 132 + 32 * 32 * 4);

    int tid = threadIdx.x;
    int tx = tid & 15, ty = tid >> 4;
    int m0 = blockIdx.x * 128;

    {   // phase 1: hpre @ W1 + heads attention + elu -> xS
        float acc[8][4];
#pragma unroll
        for (int i = 0; i < 8; i++)
#pragma unroll
            for (int j = 0; j < 4; j++) acc[i][j] = 0.f;

        for (int kc = 0; kc < 4; kc++) {
            int k0 = kc * 32;
            __syncthreads();
#pragma unroll
            for (int it = 0; it < 4; it++) {
                int idx = it * 256 + tid;
                int r = idx >> 3, kq = idx & 7;
                float4 v = *reinterpret_cast<const float4*>(&g_hpre[(m0 + r) * 128 + k0 + kq * 4]);
                As[kq * 4 + 0][r] = v.x;
                As[kq * 4 + 1][r] = v.y;
                As[kq * 4 + 2][r] = v.z;
                As[kq * 4 + 3][r] = v.w;
            }
#pragma unroll
            for (int it = 0; it < 2; it++) {
                int idx = it * 256 + tid;
                int k = idx >> 4, q = idx & 15;
                Bs[k][q] = *reinterpret_cast<const float4*>(&g_W1[(k0 + k) * 64 + q * 4]);
            }
            __syncthreads();
#pragma unroll
            for (int k = 0; k < 32; k++) {
                float4 a0 = *reinterpret_cast<const float4*>(&As[k][ty * 8]);
                float4 a1 = *reinterpret_cast<const float4*>(&As[k][ty * 8 + 4]);
                float4 b = Bs[k][tx];
                float av[8] = {a0.x, a0.y, a0.z, a0.w, a1.x, a1.y, a1.z, a1.w};
                float bw[4] = {b.x, b.y, b.z, b.w};
#pragma unroll
                for (int i = 0; i < 8; i++)
#pragma unroll
                    for (int j = 0; j < 4; j++) acc[i][j] += av[i] * bw[j];
            }
        }

        int hd = tx >> 2;
        int fb = (tx & 3) * 4;
        float asv[4], adv[4], b1v[4];
#pragma unroll
        for (int j = 0; j < 4; j++) {
            asv[j] = a_src1[hd * 16 + fb + j];
            adv[j] = a_dst1[hd * 16 + fb + j];
            b1v[j] = bias1[fb + j];
        }

        float src[8], dst[8];
#pragma unroll
        for (int n = 0; n < 8; n++) {
            float ps = 0.f, pd = 0.f;
#pragma unroll
            for (int j = 0; j < 4; j++) { ps += acc[n][j] * asv[j]; pd += acc[n][j] * adv[j]; }
            src[n] = ps; dst[n] = pd;
        }
#pragma unroll
        for (int off = 1; off <= 2; off <<= 1) {
#pragma unroll
            for (int n = 0; n < 8; n++) {
                src[n] += __shfl_xor_sync(0xffffffffu, src[n], off);
                dst[n] += __shfl_xor_sync(0xffffffffu, dst[n], off);
            }
        }
        __syncthreads();
#pragma unroll
        for (int n = 0; n < 8; n++) {
            float e[8], mx = -1e30f;
#pragma unroll
            for (int m = 0; m < 8; m++) {
                float z = src[n] + dst[m];
                z = (z >= 0.f) ? z : 0.2f * z;
                e[m] = z;
                mx = fmaxf(mx, z);
            }
            float s = 0.f;
#pragma unroll
            for (int m = 0; m < 8; m++) { e[m] = __expf(e[m] - mx); s += e[m]; }
            float inv = __fdividef(1.f, s);
            float o[4] = {0.f, 0.f, 0.f, 0.f};
#pragma unroll
            for (int m = 0; m < 8; m++) {
                float w = e[m] * inv;
#pragma unroll
                for (int j = 0; j < 4; j++) o[j] += w * acc[m][j];
            }
            float4 xo;
            float* xp = &xo.x;
#pragma unroll
            for (int j = 0; j < 4; j++) {
                float v = o[j] + b1v[j];
                xp[j] = (v > 0.f) ? v : (__expf(v) - 1.f);
            }
            *reinterpret_cast<float4*>(&xS[ty * 8 + n][tx * 4]) = xo;
        }
    }
    __syncthreads();

    {   // phase 2: xS @ w2 + group attention + h/out
        float acc[8][8];
#pragma unroll
        for (int i = 0; i < 8; i++)
#pragma unroll
            for (int j = 0; j < 8; j++) acc[i][j] = 0.f;

        for (int kc = 0; kc < 2; kc++) {
            int k0 = kc * 32;
            __syncthreads();
#pragma unroll
            for (int it = 0; it < 4; it++) {
                int idx = it * 256 + tid;
                int k = idx >> 5, q = idx & 31;
                Bs[k][q] = *reinterpret_cast<const float4*>(&w2[(k0 + k) * 128 + q * 4]);
            }
            __syncthreads();
#pragma unroll
            for (int kg = 0; kg < 8; kg++) {
                float a4[8][4];
#pragma unroll
                for (int i = 0; i < 8; i++) {
                    float4 v = *reinterpret_cast<const float4*>(&xS[ty * 8 + i][k0 + kg * 4]);
                    a4[i][0] = v.x; a4[i][1] = v.y; a4[i][2] = v.z; a4[i][3] = v.w;
                }
#pragma unroll
                for (int kk = 0; kk < 4; kk++) {
                    float4 b0 = Bs[kg * 4 + kk][tx * 2], b1 = Bs[kg * 4 + kk][tx * 2 + 1];
                    float bw[8] = {b0.x, b0.y, b0.z, b0.w, b1.x, b1.y, b1.z, b1.w};
#pragma unroll
                    for (int i = 0; i < 8; i++)
#pragma unroll
                        for (int j = 0; j < 8; j++) acc[i][j] += a4[i][kk] * bw[j];
                }
            }
        }

        int o0 = tx * 8;
        float asv[8], adv[8], b2v[8], wp0[8], wp1[8];
#pragma unroll
        for (int j = 0; j < 8; j++) {
            asv[j] = a_src2[o0 + j];
            adv[j] = a_dst2[o0 + j];
            b2v[j] = bias2[o0 + j];
            wp0[j] = W_pos[(o0 + j) * 2 + 0];
            wp1[j] = W_pos[(o0 + j) * 2 + 1];
        }

        float src[8], dst[8];
#pragma unroll
        for (int n = 0; n < 8; n++) {
            float ps = 0.f, pd = 0.f;
#pragma unroll
            for (int j = 0; j < 8; j++) { ps += acc[n][j] * asv[j]; pd += acc[n][j] * adv[j]; }
            src[n] = ps; dst[n] = pd;
        }
#pragma unroll
        for (int off = 1; off <= 8; off <<= 1) {
#pragma unroll
            for (int n = 0; n < 8; n++) {
                src[n] += __shfl_xor_sync(0xffffffffu, src[n], off);
                dst[n] += __shfl_xor_sync(0xffffffffu, dst[n], off);
            }
        }
#pragma unroll
        for (int n = 0; n < 8; n++) {
            int row = m0 + ty * 8 + n;
            float e[8], mx = -1e30f;
#pragma unroll
            for (int m = 0; m < 8; m++) {
                float z = src[n] + dst[m];
                z = (z >= 0.f) ? z : 0.2f * z;
                e[m] = z;
                mx = fmaxf(mx, z);
            }
            float s = 0.f;
#pragma unroll
            for (int m = 0; m < 8; m++) { e[m] = __expf(e[m] - mx); s += e[m]; }
            float inv = __fdividef(1.f, s);
            float o[8];
#pragma unroll
            for (int j = 0; j < 8; j++) o[j] = b2v[j];
#pragma unroll
            for (int m = 0; m < 8; m++) {
                float w = e[m] * inv;
#pragma unroll
                for (int j = 0; j < 8; j++) o[j] += w * acc[m][j];
            }
            *reinterpret_cast<float4*>(&g_h[row * 128 + o0]) = make_float4(o[0], o[1], o[2], o[3]);
            *reinterpret_cast<float4*>(&g_h[row * 128 + o0 + 4]) = make_float4(o[4], o[5], o[6], o[7]);
            float p0 = 0.f, p1 = 0.f;
#pragma unroll
            for (int j = 0; j < 8; j++) { p0 += o[j] * wp0[j]; p1 += o[j] * wp1[j]; }
#pragma unroll
            for (int off = 1; off <= 8; off <<= 1) {
                p0 += __shfl_xor_sync(0xffffffffu, p0, off);
                p1 += __shfl_xor_sync(0xffffffffu, p1, off);
            }
            if (tx == 0) {
                out[(t * BN + row) * 2 + 0] = p0 + b_pos[0];
                out[(t * BN + row) * 2 + 1] = p1 + b_pos[1];
            }
        }
    }
}

extern "C" void kernel_launch(void* const* d_in, const int* in_sizes, int n_in,
                              void* d_out, int out_size) {
    const float* action_real = (const float*)d_in[0];
    const float* h0          = (const float*)d_in[1];
    const float* pred_goal   = (const float*)d_in[2];
    const float* W_emb  = (const float*)d_in[5];
    const float* b_emb  = (const float*)d_in[6];
    const float* W_ih   = (const float*)d_in[7];
    const float* W_hh   = (const float*)d_in[8];
    const float* b_ih   = (const float*)d_in[9];
    const float* b_hh   = (const float*)d_in[10];
    const float* W_goal = (const float*)d_in[11];
    const float* b_goal = (const float*)d_in[12];
    const float* w1     = (const float*)d_in[13];
    const float* a_src1 = (const float*)d_in[14];
    const float* a_dst1 = (const float*)d_in[15];
    const float* bias1  = (const float*)d_in[16];
    const float* w2     = (const float*)d_in[17];
    const float* a_src2 = (const float*)d_in[18];
    const float* a_dst2 = (const float*)d_in[19];
    const float* bias2  = (const float*)d_in[20];
    const float* W_pos  = (const float*)d_in[21];
    const float* b_pos  = (const float*)d_in[22];
    float* out = (float*)d_out;

    cudaFuncSetAttribute(gat_kernel, cudaFuncAttributeMaxDynamicSharedMemorySize,
                         GAT_SMEM_FLOATS * (int)sizeof(float));
    cudaFuncSetAttribute(lstm_mma, cudaFuncAttributeMaxDynamicSharedMemorySize, LSTM_SMEM);

    setup_kernel<<<256, 256>>>(W_emb, b_emb, W_ih, W_hh, b_ih, b_hh, w1);
    init_kernel<<<(BN * HN + 255) / 256, 256>>>(h0);
    gls_kernel<<<(PREDN * BN * 32 + 255) / 256, 256>>>(pred_goal, W_goal, b_goal);

    for (int t = 0; t < PREDN; t++) {
        lstm_mma<<<128, 512, LSTM_SMEM>>>(t, action_real, pred_goal, W_goal, b_goal);
        gat_kernel<<<128, 256, GAT_SMEM_FLOATS * sizeof(float)>>>(
            t, a_src1, a_dst1, bias1, w2, a_src2, a_dst2, bias2, W_pos, b_pos, out);
    }
}

// round 8
// speedup vs baseline: 1.4641x; 1.1487x over previous
#include <cuda_runtime.h>
#include <cuda_bf16.h>
#include <cstdint>

#define BN 16384
#define HN 128
#define PREDN 12

__device__ __forceinline__ uint32_t smem_u32(const void* p) {
    uint32_t a;
    asm("{ .reg .u64 t; cvta.to.shared.u64 t, %1; cvt.u32.u64 %0, t; }" : "=r"(a) : "l"(p));
    return a;
}

// blocked SW128 byte offset for [128 rows][128 bf16 cols] tile (8x64-bf16 atoms)
__device__ __forceinline__ int blk_off(int r, int c) {
    int boff = ((r >> 3) + (c >> 6) * 16) * 1024 + (r & 7) * 128 + (c & 63) * 2;
    return boff ^ ((boff >> 3) & 0x70);
}

__device__ __forceinline__ void ldsm4(uint32_t* r, uint32_t addr) {
    asm volatile("ldmatrix.sync.aligned.m8n8.x4.shared.b16 {%0,%1,%2,%3}, [%4];"
                 : "=r"(r[0]), "=r"(r[1]), "=r"(r[2]), "=r"(r[3]) : "r"(addr));
}
__device__ __forceinline__ void mma16816(float* c, const uint32_t* a, const uint32_t* b) {
    asm volatile(
        "mma.sync.aligned.m16n8k16.row.col.f32.bf16.bf16.f32 "
        "{%0,%1,%2,%3}, {%4,%5,%6,%7}, {%8,%9}, {%0,%1,%2,%3};"
        : "+f"(c[0]), "+f"(c[1]), "+f"(c[2]), "+f"(c[3])
        : "r"(a[0]), "r"(a[1]), "r"(a[2]), "r"(a[3]), "r"(b[0]), "r"(b[1]));
}
#define CP_ASYNC16(dst, src) \
    asm volatile("cp.async.cg.shared.global [%0], [%1], 16;" :: "r"(dst), "l"(src))
#define CP_COMMIT asm volatile("cp.async.commit_group;" ::: "memory")
#define CP_WAIT1 asm volatile("cp.async.wait_group 1;" ::: "memory")
#define CP_WAIT0 asm volatile("cp.async.wait_group 0;" ::: "memory")

// ==================== device scratch ====================
__device__ __align__(16) unsigned short g_WpHi[4][16384]; // bf16 hi, [n 128][k 128] swizzled per chunk
__device__ __align__(16) unsigned short g_WpLo[4][16384]; // bf16 lo
__device__ float g_Mc[2 * 512];
__device__ float g_bv[512];
__device__ float g_W1[128 * 64];
__device__ float g_h[BN * HN];      // row-major [row][128]
__device__ float g_c[BN * HN];      // COLUMN-major [u][BN]  (coalesced epilogue)
__device__ float g_hpre[BN * HN];   // COLUMN-major [k][BN]  (coalesced epilogue + gat load)
__device__ float g_gls[PREDN * BN];

__device__ __forceinline__ float fsig(float x) { return __fdividef(1.f, 1.f + __expf(-x)); }
__device__ __forceinline__ float ftanh(float x) { return __fdividef(2.f, 1.f + __expf(-2.f * x)) - 1.f; }

// ==================== setup ====================
__global__ void setup_kernel(const float* __restrict__ W_emb, const float* __restrict__ b_emb,
                             const float* __restrict__ W_ih, const float* __restrict__ W_hh,
                             const float* __restrict__ b_ih, const float* __restrict__ b_hh,
                             const float* __restrict__ w1) {
    int idx = blockIdx.x * 256 + threadIdx.x;
    if (idx < 128 * 512) {
        int k = idx >> 9, n = idx & 511;       // n = unit*4 + gate (interleaved)
        int u = n >> 2, g = n & 3;
        float v = W_hh[(g * 128 + u) * 128 + k];
        __nv_bfloat16 bh = __float2bfloat16(v);
        __nv_bfloat16 bl = __float2bfloat16(v - __bfloat162float(bh));
        int chunk = n >> 7, nr = n & 127;
        int sw = blk_off(nr, k);               // B stored n-major: [n][k]
        g_WpHi[chunk][sw >> 1] = __bfloat16_as_ushort(bh);
        g_WpLo[chunk][sw >> 1] = __bfloat16_as_ushort(bl);
    }
    if (idx < 128 * 64) {
        int c = idx >> 6, kf = idx & 63;
        int hd = kf >> 4, f = kf & 15;
        g_W1[idx] = w1[(hd * 128 + c) * 16 + f];
    }
    if (idx < 512) {
        int n = idx;
        int u = n >> 2, g = n & 3;
        int row = g * 128 + u;
        float m0 = 0.f, m1 = 0.f, bb = 0.f;
        for (int e = 0; e < 64; e++) {
            float wih = W_ih[row * 64 + e];
            m0 += W_emb[e] * wih;
            m1 += W_emb[64 + e] * wih;
            bb += b_emb[e] * wih;
        }
        g_Mc[n] = m0;
        g_Mc[512 + n] = m1;
        g_bv[n] = bb + b_ih[row] + b_hh[row];
    }
}

__global__ void init_kernel(const float* __restrict__ h0) {
    int i = blockIdx.x * 256 + threadIdx.x;
    if (i < BN * HN) { g_h[i] = h0[i]; g_c[i] = 0.f; }
}

__global__ void gls_kernel(const float* __restrict__ pred_goal, const float* __restrict__ W_goal,
                           const float* __restrict__ b_goal) {
    int gw = (blockIdx.x * 256 + threadIdx.x) >> 5;
    int lane = threadIdx.x & 31;
    if (gw >= PREDN * BN) return;
    float pg0 = pred_goal[gw * 2 + 0], pg1 = pred_goal[gw * 2 + 1];
    float z[4];
    float m = -1e30f;
#pragma unroll
    for (int q = 0; q < 4; q++) {
        int u = lane + q * 32;
        z[q] = pg0 * W_goal[u] + pg1 * W_goal[128 + u] + b_goal[u];
        m = fmaxf(m, z[q]);
    }
#pragma unroll
    for (int s = 16; s > 0; s >>= 1) m = fmaxf(m, __shfl_xor_sync(0xffffffffu, m, s));
    float sum = 0.f;
#pragma unroll
    for (int q = 0; q < 4; q++) sum += __expf(z[q] - m);
#pragma unroll
    for (int s = 16; s > 0; s >>= 1) sum += __shfl_xor_sync(0xffffffffu, sum, s);
    if (lane == 0) g_gls[gw] = m + __logf(sum);
}

// ==================== LSTM via mma.sync bf16 split, 512 thr + cp.async ====================
// smem: A_hi 32K | A_lo 32K | Bbuf0 (hi32K+lo32K) | Bbuf1 (hi32K+lo32K) = 192KB
#define SM_AHI 0
#define SM_ALO 32768
#define SM_B0  65536
#define LSTM_SMEM 196608

__global__ __launch_bounds__(512, 1) void lstm_mma(int t,
                                                   const float* __restrict__ action_real,
                                                   const float* __restrict__ pred_goal,
                                                   const float* __restrict__ W_goal,
                                                   const float* __restrict__ b_goal) {
    extern __shared__ __align__(1024) char sm[];
    uint32_t sb = smem_u32(sm);
    int tid = threadIdx.x;
    int w = tid >> 5, lane = tid & 31;
    int g = lane >> 2, q = lane & 3;
    int parity = q & 1, uloc = q >> 1;
    int wm = w >> 1, wn = w & 1;     // 8 m16 tiles x 2 n64 halves
    int m0 = blockIdx.x * 128;

    // ---- prefetch B chunk 0 into buf0 ----
    {
        const char* srcH = (const char*)g_WpHi[0];
        const char* srcL = (const char*)g_WpLo[0];
        uint32_t dH = sb + SM_B0;
        uint32_t dL = dH + 32768;
#pragma unroll
        for (int it = 0; it < 4; it++) {
            int off = (it * 512 + tid) * 16;
            CP_ASYNC16(dH + off, srcH + off);
            CP_ASYNC16(dL + off, srcL + off);
        }
        CP_COMMIT;
    }

    // ---- convert A = g_h[m0..m0+127][:] to bf16 hi/lo swizzled (overlaps cp.async) ----
#pragma unroll
    for (int it = 0; it < 8; it++) {
        int idx = it * 512 + tid;
        int r = idx >> 5;
        int c4 = (idx & 31) * 4;
        float4 v = *reinterpret_cast<const float4*>(&g_h[(m0 + r) * 128 + c4]);
        float a[4] = {v.x, v.y, v.z, v.w};
        unsigned short hs[4], ls[4];
#pragma unroll
        for (int p = 0; p < 4; p++) {
            __nv_bfloat16 bh = __float2bfloat16(a[p]);
            __nv_bfloat16 bl = __float2bfloat16(a[p] - __bfloat162float(bh));
            hs[p] = __bfloat16_as_ushort(bh);
            ls[p] = __bfloat16_as_ushort(bl);
        }
        int sw = blk_off(r, c4);
        *reinterpret_cast<uint2*>(sm + SM_AHI + sw) =
            make_uint2((uint32_t)hs[0] | ((uint32_t)hs[1] << 16),
                       (uint32_t)hs[2] | ((uint32_t)hs[3] << 16));
        *reinterpret_cast<uint2*>(sm + SM_ALO + sw) =
            make_uint2((uint32_t)ls[0] | ((uint32_t)ls[1] << 16),
                       (uint32_t)ls[2] | ((uint32_t)ls[3] << 16));
    }

    // ---- per-row epilogue constants (rows rg and rg+8) ----
    int rg = m0 + wm * 16 + g;
    float2 arr[2], pgr[2];
    float glr[2];
#pragma unroll
    for (int mt = 0; mt < 2; mt++) {
        int row = rg + mt * 8;
        arr[mt] = *reinterpret_cast<const float2*>(&action_real[((8 + t) * BN + row) * 2]);
        pgr[mt] = *reinterpret_cast<const float2*>(&pred_goal[(t * BN + row) * 2]);
        glr[mt] = g_gls[t * BN + row];
    }

    int a_row = lane & 15;
    int a_khalf = (lane >> 4) * 8;
    int b_nloc = wn * 64 + (lane >> 4) * 8 + (lane & 7);
    int b_khalf = ((lane >> 3) & 1) * 8;

    for (int nc = 0; nc < 4; nc++) {
        uint32_t bbase = sb + SM_B0 + (nc & 1) * 65536;
        if (nc < 3) {   // prefetch next chunk into other buf (safe: freed by prev end-sync)
            const char* srcH = (const char*)g_WpHi[nc + 1];
            const char* srcL = (const char*)g_WpLo[nc + 1];
            uint32_t dH = sb + SM_B0 + (((nc + 1) & 1) * 65536);
            uint32_t dL = dH + 32768;
#pragma unroll
            for (int it = 0; it < 4; it++) {
                int off = (it * 512 + tid) * 16;
                CP_ASYNC16(dH + off, srcH + off);
                CP_ASYNC16(dL + off, srcL + off);
            }
            CP_COMMIT;
            CP_WAIT1;
        } else {
            CP_WAIT0;
        }
        __syncthreads();   // chunk nc visible to all warps (covers A convert on nc=0)

        float acc[8][4];
#pragma unroll
        for (int j = 0; j < 8; j++)
#pragma unroll
            for (int p = 0; p < 4; p++) acc[j][p] = 0.f;

#pragma unroll
        for (int ks = 0; ks < 8; ks++) {
            int kc = ks * 16;
            uint32_t ahi[4], alo[4];
            uint32_t ad = sb + SM_AHI + blk_off(wm * 16 + a_row, kc + a_khalf);
            ldsm4(ahi, ad);
            ldsm4(alo, ad + 32768);
            uint32_t bhi[4][4], blo[4][4];
#pragma unroll
            for (int pr = 0; pr < 4; pr++) {
                uint32_t bd = bbase + blk_off(b_nloc + pr * 16, kc + b_khalf);
                ldsm4(bhi[pr], bd);
                ldsm4(blo[pr], bd + 32768);
            }
#pragma unroll
            for (int nt = 0; nt < 8; nt++) {
                int pr = nt >> 1, hf = (nt & 1) * 2;
                mma16816(acc[nt], ahi, &bhi[pr][hf]);
                mma16816(acc[nt], ahi, &blo[pr][hf]);
                mma16816(acc[nt], alo, &bhi[pr][hf]);
            }
        }

        // ---- epilogue: pair-exchange gates, LSTM cell + goal gate (rows rg, rg+8) ----
        // g_c / g_hpre are COLUMN-major: [u][BN] -> warp stores hit 2 consecutive-row
        // 64B segments per instruction instead of 32 scattered sectors.
#pragma unroll
        for (int nt = 0; nt < 8; nt++) {
            int u = nc * 32 + wn * 16 + nt * 2 + uloc;
            int n4 = u * 4;
            float4 mA = *reinterpret_cast<const float4*>(&g_Mc[n4]);
            float4 mB = *reinterpret_cast<const float4*>(&g_Mc[512 + n4]);
            float4 bv = *reinterpret_cast<const float4*>(&g_bv[n4]);
            float wga = W_goal[u], wgb = W_goal[128 + u], bgu = b_goal[u];
            float c0 = acc[nt][0], c1 = acc[nt][1], c2 = acc[nt][2], c3 = acc[nt][3];
            float x0 = __shfl_xor_sync(0xffffffffu, c0, 1);
            float x1 = __shfl_xor_sync(0xffffffffu, c1, 1);
            float x2 = __shfl_xor_sync(0xffffffffu, c2, 1);
            float x3 = __shfl_xor_sync(0xffffffffu, c3, 1);
#pragma unroll
            for (int mt = 0; mt < 2; mt++) {
                float gi, gf, gg2, go;
                if (parity == 0) {
                    gi = (mt == 0) ? c0 : c2; gf = (mt == 0) ? c1 : c3;
                    gg2 = (mt == 0) ? x0 : x2; go = (mt == 0) ? x1 : x3;
                } else {
                    gi = (mt == 0) ? x0 : x2; gf = (mt == 0) ? x1 : x3;
                    gg2 = (mt == 0) ? c0 : c2; go = (mt == 0) ? c1 : c3;
                }
                int row = rg + mt * 8;
                float ar0 = arr[mt].x, ar1 = arr[mt].y;
                gi += ar0 * mA.x + ar1 * mB.x + bv.x;
                gf += ar0 * mA.y + ar1 * mB.y + bv.y;
                gg2 += ar0 * mA.z + ar1 * mB.z + bv.z;
                go += ar0 * mA.w + ar1 * mB.w + bv.w;
                float cold = g_c[u * BN + row];
                float cn = fsig(gf) * cold + fsig(gi) * ftanh(gg2);
                float hh = fsig(go) * ftanh(cn);
                float z = pgr[mt].x * wga + pgr[mt].y * wgb + bgu;
                hh *= __expf(z - glr[mt]);
                g_c[u * BN + row] = cn;
                g_hpre[u * BN + row] = hh;
            }
        }
        __syncthreads();   // all warps done with buf nc&1 before it's overwritten
    }
}

// ==================== fused GAT ====================
#define GAT_SMEM_FLOATS (32 * 132 + 32 * 32 * 4 + 128 * 68)
__global__ __launch_bounds__(256, 2) void gat_kernel(int t,
                                                     const float* __restrict__ a_src1,
                                                     const float* __restrict__ a_dst1,
                                                     const float* __restrict__ bias1,
                                                     const float* __restrict__ w2,
                                                     const float* __restrict__ a_src2,
                                                     const float* __restrict__ a_dst2,
                                                     const float* __restrict__ bias2,
                                                     const float* __restrict__ W_pos,
                                                     const float* __restrict__ b_pos,
                                                     float* __restrict__ out) {
    extern __shared__ __align__(16) float smem[];
    float (*As)[132] = reinterpret_cast<float(*)[132]>(smem);
    float4 (*Bs)[32] = reinterpret_cast<float4(*)[32]>(smem + 32 * 132);
    float (*xS)[68] = reinterpret_cast<float(*)[68]>(smem + 32 * 132 + 32 * 32 * 4);

    int tid = threadIdx.x;
    int tx = tid & 15, ty = tid >> 4;
    int m0 = blockIdx.x * 128;

    {   // phase 1: hpre @ W1 + heads attention + elu -> xS
        float acc[8][4];
#pragma unroll
        for (int i = 0; i < 8; i++)
#pragma unroll
            for (int j = 0; j < 4; j++) acc[i][j] = 0.f;

        for (int kc = 0; kc < 4; kc++) {
            int k0 = kc * 32;
            __syncthreads();
            // g_hpre is column-major [k][BN]: direct contiguous float4 into As[k][r]
#pragma unroll
            for (int it = 0; it < 4; it++) {
                int idx = it * 256 + tid;
                int k = idx >> 5, rq = idx & 31;
                float4 v = *reinterpret_cast<const float4*>(&g_hpre[(k0 + k) * BN + m0 + rq * 4]);
                *reinterpret_cast<float4*>(&As[k][rq * 4]) = v;
            }
#pragma unroll
            for (int it = 0; it < 2; it++) {
                int idx = it * 256 + tid;
                int k = idx >> 4, q = idx & 15;
                Bs[k][q] = *reinterpret_cast<const float4*>(&g_W1[(k0 + k) * 64 + q * 4]);
            }
            __syncthreads();
#pragma unroll
            for (int k = 0; k < 32; k++) {
                float4 a0 = *reinterpret_cast<const float4*>(&As[k][ty * 8]);
                float4 a1 = *reinterpret_cast<const float4*>(&As[k][ty * 8 + 4]);
                float4 b = Bs[k][tx];
                float av[8] = {a0.x, a0.y, a0.z, a0.w, a1.x, a1.y, a1.z, a1.w};
                float bw[4] = {b.x, b.y, b.z, b.w};
#pragma unroll
                for (int i = 0; i < 8; i++)
#pragma unroll
                    for (int j = 0; j < 4; j++) acc[i][j] += av[i] * bw[j];
            }
        }

        int hd = tx >> 2;
        int fb = (tx & 3) * 4;
        float asv[4], adv[4], b1v[4];
#pragma unroll
        for (int j = 0; j < 4; j++) {
            asv[j] = a_src1[hd * 16 + fb + j];
            adv[j] = a_dst1[hd * 16 + fb + j];
            b1v[j] = bias1[fb + j];
        }

        float src[8], dst[8];
#pragma unroll
        for (int n = 0; n < 8; n++) {
            float ps = 0.f, pd = 0.f;
#pragma unroll
            for (int j = 0; j < 4; j++) { ps += acc[n][j] * asv[j]; pd += acc[n][j] * adv[j]; }
            src[n] = ps; dst[n] = pd;
        }
#pragma unroll
        for (int off = 1; off <= 2; off <<= 1) {
#pragma unroll
            for (int n = 0; n < 8; n++) {
                src[n] += __shfl_xor_sync(0xffffffffu, src[n], off);
                dst[n] += __shfl_xor_sync(0xffffffffu, dst[n], off);
            }
        }
        __syncthreads();
#pragma unroll
        for (int n = 0; n < 8; n++) {
            float e[8], mx = -1e30f;
#pragma unroll
            for (int m = 0; m < 8; m++) {
                float z = src[n] + dst[m];
                z = (z >= 0.f) ? z : 0.2f * z;
                e[m] = z;
                mx = fmaxf(mx, z);
            }
            float s = 0.f;
#pragma unroll
            for (int m = 0; m < 8; m++) { e[m] = __expf(e[m] - mx); s += e[m]; }
            float inv = __fdividef(1.f, s);
            float o[4] = {0.f, 0.f, 0.f, 0.f};
#pragma unroll
            for (int m = 0; m < 8; m++) {
                float w = e[m] * inv;
#pragma unroll
                for (int j = 0; j < 4; j++) o[j] += w * acc[m][j];
            }
            float4 xo;
            float* xp = &xo.x;
#pragma unroll
            for (int j = 0; j < 4; j++) {
                float v = o[j] + b1v[j];
                xp[j] = (v > 0.f) ? v : (__expf(v) - 1.f);
            }
            *reinterpret_cast<float4*>(&xS[ty * 8 + n][tx * 4]) = xo;
        }
    }
    __syncthreads();

    {   // phase 2: xS @ w2 + group attention + h/out
        float acc[8][8];
#pragma unroll
        for (int i = 0; i < 8; i++)
#pragma unroll
            for (int j = 0; j < 8; j++) acc[i][j] = 0.f;

        for (int kc = 0; kc < 2; kc++) {
            int k0 = kc * 32;
            __syncthreads();
#pragma unroll
            for (int it = 0; it < 4; it++) {
                int idx = it * 256 + tid;
                int k = idx >> 5, q = idx & 31;
                Bs[k][q] = *reinterpret_cast<const float4*>(&w2[(k0 + k) * 128 + q * 4]);
            }
            __syncthreads();
#pragma unroll
            for (int kg = 0; kg < 8; kg++) {
                float a4[8][4];
#pragma unroll
                for (int i = 0; i < 8; i++) {
                    float4 v = *reinterpret_cast<const float4*>(&xS[ty * 8 + i][k0 + kg * 4]);
                    a4[i][0] = v.x; a4[i][1] = v.y; a4[i][2] = v.z; a4[i][3] = v.w;
                }
#pragma unroll
                for (int kk = 0; kk < 4; kk++) {
                    float4 b0 = Bs[kg * 4 + kk][tx * 2], b1 = Bs[kg * 4 + kk][tx * 2 + 1];
                    float bw[8] = {b0.x, b0.y, b0.z, b0.w, b1.x, b1.y, b1.z, b1.w};
#pragma unroll
                    for (int i = 0; i < 8; i++)
#pragma unroll
                        for (int j = 0; j < 8; j++) acc[i][j] += a4[i][kk] * bw[j];
                }
            }
        }

        int o0 = tx * 8;
        float asv[8], adv[8], b2v[8], wp0[8], wp1[8];
#pragma unroll
        for (int j = 0; j < 8; j++) {
            asv[j] = a_src2[o0 + j];
            adv[j] = a_dst2[o0 + j];
            b2v[j] = bias2[o0 + j];
            wp0[j] = W_pos[(o0 + j) * 2 + 0];
            wp1[j] = W_pos[(o0 + j) * 2 + 1];
        }

        float src[8], dst[8];
#pragma unroll
        for (int n = 0; n < 8; n++) {
            float ps = 0.f, pd = 0.f;
#pragma unroll
            for (int j = 0; j < 8; j++) { ps += acc[n][j] * asv[j]; pd += acc[n][j] * adv[j]; }
            src[n] = ps; dst[n] = pd;
        }
#pragma unroll
        for (int off = 1; off <= 8; off <<= 1) {
#pragma unroll
            for (int n = 0; n < 8; n++) {
                src[n] += __shfl_xor_sync(0xffffffffu, src[n], off);
                dst[n] += __shfl_xor_sync(0xffffffffu, dst[n], off);
            }
        }
#pragma unroll
        for (int n = 0; n < 8; n++) {
            int row = m0 + ty * 8 + n;
            float e[8], mx = -1e30f;
#pragma unroll
            for (int m = 0; m < 8; m++) {
                float z = src[n] + dst[m];
                z = (z >= 0.f) ? z : 0.2f * z;
                e[m] = z;
                mx = fmaxf(mx, z);
            }
            float s = 0.f;
#pragma unroll
            for (int m = 0; m < 8; m++) { e[m] = __expf(e[m] - mx); s += e[m]; }
            float inv = __fdividef(1.f, s);
            float o[8];
#pragma unroll
            for (int j = 0; j < 8; j++) o[j] = b2v[j];
#pragma unroll
            for (int m = 0; m < 8; m++) {
                float w = e[m] * inv;
#pragma unroll
                for (int j = 0; j < 8; j++) o[j] += w * acc[m][j];
            }
            *reinterpret_cast<float4*>(&g_h[row * 128 + o0]) = make_float4(o[0], o[1], o[2], o[3]);
            *reinterpret_cast<float4*>(&g_h[row * 128 + o0 + 4]) = make_float4(o[4], o[5], o[6], o[7]);
            float p0 = 0.f, p1 = 0.f;
#pragma unroll
            for (int j = 0; j < 8; j++) { p0 += o[j] * wp0[j]; p1 += o[j] * wp1[j]; }
#pragma unroll
            for (int off = 1; off <= 8; off <<= 1) {
                p0 += __shfl_xor_sync(0xffffffffu, p0, off);
                p1 += __shfl_xor_sync(0xffffffffu, p1, off);
            }
            if (tx == 0) {
                out[(t * BN + row) * 2 + 0] = p0 + b_pos[0];
                out[(t * BN + row) * 2 + 1] = p1 + b_pos[1];
            }
        }
    }
}

extern "C" void kernel_launch(void* const* d_in, const int* in_sizes, int n_in,
                              void* d_out, int out_size) {
    const float* action_real = (const float*)d_in[0];
    const float* h0          = (const float*)d_in[1];
    const float* pred_goal   = (const float*)d_in[2];
    const float* W_emb  = (const float*)d_in[5];
    const float* b_emb  = (const float*)d_in[6];
    const float* W_ih   = (const float*)d_in[7];
    const float* W_hh   = (const float*)d_in[8];
    const float* b_ih   = (const float*)d_in[9];
    const float* b_hh   = (const float*)d_in[10];
    const float* W_goal = (const float*)d_in[11];
    const float* b_goal = (const float*)d_in[12];
    const float* w1     = (const float*)d_in[13];
    const float* a_src1 = (const float*)d_in[14];
    const float* a_dst1 = (const float*)d_in[15];
    const float* bias1  = (const float*)d_in[16];
    const float* w2     = (const float*)d_in[17];
    const float* a_src2 = (const float*)d_in[18];
    const float* a_dst2 = (const float*)d_in[19];
    const float* bias2  = (const float*)d_in[20];
    const float* W_pos  = (const float*)d_in[21];
    const float* b_pos  = (const float*)d_in[22];
    float* out = (float*)d_out;

    cudaFuncSetAttribute(gat_kernel, cudaFuncAttributeMaxDynamicSharedMemorySize,
                         GAT_SMEM_FLOATS * (int)sizeof(float));
    cudaFuncSetAttribute(lstm_mma, cudaFuncAttributeMaxDynamicSharedMemorySize, LSTM_SMEM);

    setup_kernel<<<256, 256>>>(W_emb, b_emb, W_ih, W_hh, b_ih, b_hh, w1);
    init_kernel<<<(BN * HN + 255) / 256, 256>>>(h0);
    gls_kernel<<<(PREDN * BN * 32 + 255) / 256, 256>>>(pred_goal, W_goal, b_goal);

    for (int t = 0; t < PREDN; t++) {
        lstm_mma<<<128, 512, LSTM_SMEM>>>(t, action_real, pred_goal, W_goal, b_goal);
        gat_kernel<<<128, 256, GAT_SMEM_FLOATS * sizeof(float)>>>(
            t, a_src1, a_dst1, bias1, w2, a_src2, a_dst2, bias2, W_pos, b_pos, out);
    }
}